// round 7
// baseline (speedup 1.0000x reference)
#include <cuda_runtime.h>
#include <math.h>

#define N_NODES 50000
#define N_EDGES 800000
#define D 128
#define HEADS 4
#define SCALEF 0.17677669529663687f   // 32^-0.5
#define EPSF 1e-7f

// ---------------- static device scratch ----------------
__device__ float g_xtan[(size_t)N_NODES * D];
__device__ float g_qkv[(size_t)N_NODES * 3 * D];   // per node: Q|K|V
__device__ float g_agg[(size_t)N_NODES * D];
__device__ float g_denom[(size_t)N_NODES * HEADS];
__device__ float g_otan[(size_t)N_NODES * D];
__device__ int   g_row[N_EDGES];
__device__ int   g_col[N_EDGES];
__device__ int   g_is64;

// ---------------- edge dtype detect + convert ----------------
__global__ void k_detect_edges(const unsigned int* __restrict__ w) {
    if (threadIdx.x == 0 && blockIdx.x == 0) {
        int all0 = 1;
        #pragma unroll
        for (int i = 0; i < 32; i++) all0 &= (w[2 * i + 1] == 0u);
        g_is64 = all0;
    }
}
__global__ void k_cvt_edges(const void* __restrict__ eiv) {
    int e = blockIdx.x * blockDim.x + threadIdx.x;
    if (e >= N_EDGES) return;
    if (g_is64) {
        const long long* ei = (const long long*)eiv;
        g_row[e] = (int)ei[e];
        g_col[e] = (int)ei[N_EDGES + e];
    } else {
        const int* ei = (const int*)eiv;
        g_row[e] = ei[e];
        g_col[e] = ei[N_EDGES + e];
    }
}

// ---------------- init ----------------
__global__ void k_init() {
    int idx = blockIdx.x * blockDim.x + threadIdx.x;
    if (idx < N_NODES * D) g_agg[idx] = 0.0f;
    if (idx < N_NODES * HEADS) g_denom[idx] = 0.0f;
}

// ---------------- Lorentz log map at origin (c=1), warp per node ----------------
__global__ void k_logmap(const float* __restrict__ x) {
    int gw = (blockIdx.x * blockDim.x + threadIdx.x) >> 5;
    int lane = threadIdx.x & 31;
    if (gw >= N_NODES) return;
    const float* xr = x + (size_t)gw * 129;
    float a0 = xr[1 + 4 * lane + 0];
    float a1 = xr[1 + 4 * lane + 1];
    float a2 = xr[1 + 4 * lane + 2];
    float a3 = xr[1 + 4 * lane + 3];
    float ss = a0 * a0 + a1 * a1 + a2 * a2 + a3 * a3;
    #pragma unroll
    for (int o = 16; o >= 1; o >>= 1) ss += __shfl_xor_sync(0xFFFFFFFFu, ss, o);
    float norm = sqrtf(ss + EPSF);
    float fac = acoshf(fmaxf(xr[0], 1.0f + EPSF)) / norm;
    float4 outv = make_float4(fac * a0, fac * a1, fac * a2, fac * a3);
    *(float4*)(g_xtan + (size_t)gw * D + 4 * lane) = outv;
}

// ---------------- tiled SGEMM: C[:, colOff+0..127] = A(Mx128) @ B^T ----------------
// NOTE: A and C are REAL device addresses resolved via cudaGetSymbolAddress.
template<bool DIV, bool BIAS>
__global__ __launch_bounds__(256)
void k_gemm(const float* __restrict__ A, const float* __restrict__ B,
            const float* __restrict__ bias, float* __restrict__ C,
            int M, int NC, int colOff) {
    const int BM = 64, BN = 64, BK = 16;
    __shared__ float As[BK][68];
    __shared__ float Bs[BK][68];
    int t = threadIdx.x;
    int rowBase = blockIdx.x * BM;
    int colBase = blockIdx.y * BN;
    int tx = t & 15, ty = t >> 4;
    float acc[4][4] = {};
    for (int kk = 0; kk < 128; kk += BK) {
        #pragma unroll
        for (int i = 0; i < 4; i++) {
            int idx = t + i * 256;
            int m = idx >> 4, k = idx & 15;
            int r = rowBase + m;
            float v = 0.0f;
            if (r < M) {
                v = A[(size_t)r * 128 + kk + k];
                if (DIV) {
                    float dn = g_denom[r * 4 + ((kk + k) >> 5)];
                    v = (dn > 0.0f) ? (v / dn) : 0.0f;
                }
            }
            As[k][m] = v;
        }
        #pragma unroll
        for (int i = 0; i < 4; i++) {
            int idx = t + i * 256;
            int j = idx >> 4, k = idx & 15;
            Bs[k][j] = B[(size_t)(colBase + j) * 128 + kk + k];
        }
        __syncthreads();
        #pragma unroll
        for (int k = 0; k < BK; k++) {
            float4 a4 = *(const float4*)&As[k][ty * 4];
            float4 b4 = *(const float4*)&Bs[k][tx * 4];
            float av[4] = {a4.x, a4.y, a4.z, a4.w};
            float bv[4] = {b4.x, b4.y, b4.z, b4.w};
            #pragma unroll
            for (int i = 0; i < 4; i++)
                #pragma unroll
                for (int j = 0; j < 4; j++)
                    acc[i][j] = fmaf(av[i], bv[j], acc[i][j]);
        }
        __syncthreads();
    }
    #pragma unroll
    for (int i = 0; i < 4; i++) {
        int r = rowBase + ty * 4 + i;
        if (r >= M) continue;
        #pragma unroll
        for (int j = 0; j < 4; j++) {
            int c = colBase + tx * 4 + j;
            float v = acc[i][j];
            if (BIAS) v += bias[c];
            C[(size_t)r * NC + colOff + c] = v;
        }
    }
}

// ---------------- fused edge pass, warp per edge ----------------
__global__ __launch_bounds__(256)
void k_edge() {
    int gw = (blockIdx.x * blockDim.x + threadIdx.x) >> 5;
    int lane = threadIdx.x & 31;
    if (gw >= N_EDGES) return;
    int row = g_row[gw];
    int col = g_col[gw];
    const float* base_c = g_qkv + (size_t)col * 384;
    const float* base_r = g_qkv + (size_t)row * 384;
    float4 q = *(const float4*)(base_c + 4 * lane);
    float4 k4 = *(const float4*)(base_r + 128 + 4 * lane);
    float p = q.x * k4.x + q.y * k4.y + q.z * k4.z + q.w * k4.w;
    p += __shfl_xor_sync(0xFFFFFFFFu, p, 4);
    p += __shfl_xor_sync(0xFFFFFFFFu, p, 2);
    p += __shfl_xor_sync(0xFFFFFFFFu, p, 1);
    float ev = expf(p * SCALEF);   // max-shift dropped: cancels exactly in agg/denom
    int h = lane >> 3;
    if ((lane & 7) == 0) atomicAdd(&g_denom[col * 4 + h], ev);
    float4 v4 = *(const float4*)(base_r + 256 + 4 * lane);
    float* ag = g_agg + (size_t)col * 128 + 4 * lane;
    atomicAdd(ag + 0, ev * v4.x);
    atomicAdd(ag + 1, ev * v4.y);
    atomicAdd(ag + 2, ev * v4.z);
    atomicAdd(ag + 3, ev * v4.w);
}

// ---------------- Lorentz exp map at origin (c=1), warp per node ----------------
__global__ void k_expmap(float* __restrict__ out) {
    int gw = (blockIdx.x * blockDim.x + threadIdx.x) >> 5;
    int lane = threadIdx.x & 31;
    if (gw >= N_NODES) return;
    const float* vr = g_otan + (size_t)gw * D;
    float4 v = *(const float4*)(vr + 4 * lane);
    float ss = v.x * v.x + v.y * v.y + v.z * v.z + v.w * v.w;
    #pragma unroll
    for (int o = 16; o >= 1; o >>= 1) ss += __shfl_xor_sync(0xFFFFFFFFu, ss, o);
    float r = sqrtf(ss + EPSF);
    float x0 = coshf(r);
    float fac = sinhf(r) / r;
    float* orow = out + (size_t)gw * 129;
    if (lane == 0) orow[0] = x0;
    orow[1 + 4 * lane + 0] = fac * v.x;
    orow[1 + 4 * lane + 1] = fac * v.y;
    orow[1 + 4 * lane + 2] = fac * v.z;
    orow[1 + 4 * lane + 3] = fac * v.w;
}

// ---------------- launch ----------------
extern "C" void kernel_launch(void* const* d_in, const int* in_sizes, int n_in,
                              void* d_out, int out_size) {
    const float* x  = (const float*)d_in[0];
    const void*  ei = (const void*)d_in[1];
    const float* Wq = (const float*)d_in[2];
    const float* Wk = (const float*)d_in[3];
    const float* Wv = (const float*)d_in[4];
    const float* Wo = (const float*)d_in[5];
    const float* bo = (const float*)d_in[6];
    float* out      = (float*)d_out;
    (void)in_sizes; (void)n_in; (void)out_size;

    // CRITICAL: resolve REAL device addresses of __device__ globals.
    // Passing the symbol directly as a kernel arg passes the host shadow
    // address, which GB300's ATS happily dereferences into host memory.
    float *xtan, *qkv, *agg, *otan;
    cudaGetSymbolAddress((void**)&xtan, g_xtan);
    cudaGetSymbolAddress((void**)&qkv,  g_qkv);
    cudaGetSymbolAddress((void**)&agg,  g_agg);
    cudaGetSymbolAddress((void**)&otan, g_otan);

    k_detect_edges<<<1, 32>>>((const unsigned int*)ei);
    k_cvt_edges<<<(N_EDGES + 255) / 256, 256>>>(ei);
    k_init<<<(N_NODES * D + 255) / 256, 256>>>();
    k_logmap<<<(N_NODES * 32 + 255) / 256, 256>>>(x);
    // Q, K, V projections
    {
        dim3 grid((N_NODES + 63) / 64, 2);
        k_gemm<false, false><<<grid, 256>>>(xtan, Wq, nullptr, qkv, N_NODES, 384, 0);
        k_gemm<false, false><<<grid, 256>>>(xtan, Wk, nullptr, qkv, N_NODES, 384, 128);
        k_gemm<false, false><<<grid, 256>>>(xtan, Wv, nullptr, qkv, N_NODES, 384, 256);
    }
    k_edge<<<(N_EDGES * 32 + 255) / 256, 256>>>();
    // out_tan = (agg/denom) @ Wo^T + bo
    {
        dim3 grid((N_NODES + 63) / 64, 2);
        k_gemm<true, true><<<grid, 256>>>(agg, Wo, bo, otan, N_NODES, 128, 0);
    }
    k_expmap<<<(N_NODES * 32 + 255) / 256, 256>>>(out);
}

// round 8
// speedup vs baseline: 1.4421x; 1.4421x over previous
#include <cuda_runtime.h>
#include <math.h>

#define N_NODES 50000
#define N_EDGES 800000
#define D 128
#define HEADS 4
#define SCALEF 0.17677669529663687f   // 32^-0.5
#define EPSF 1e-7f

// ---------------- static device scratch ----------------
__device__ float g_xtan[(size_t)N_NODES * D];
__device__ float g_qkv[(size_t)N_NODES * 3 * D];   // per node: Q|K|V
__device__ float g_agg[(size_t)N_NODES * D];       // attention output, pre-divided by denom
__device__ float g_otan[(size_t)N_NODES * D];
__device__ int   g_rowbuf[N_EDGES];
__device__ int   g_colbuf[N_EDGES];
__device__ int   g_cnt[N_NODES];                   // per-dst degree
__device__ int   g_off[N_NODES + 1];               // CSR offsets
__device__ int   g_cur[N_NODES];                   // scatter cursors
__device__ int   g_esort[N_EDGES];                 // src node ids grouped by dst
__device__ int   g_is64;

// ---------------- edge dtype detect ----------------
__global__ void k_detect_edges(const unsigned int* __restrict__ w) {
    if (threadIdx.x == 0 && blockIdx.x == 0) {
        int all0 = 1;
        #pragma unroll
        for (int i = 0; i < 32; i++) all0 &= (w[2 * i + 1] == 0u);
        g_is64 = all0;
    }
}

// ---------------- zero histogram ----------------
__global__ void k_zero_cnt() {
    int i = blockIdx.x * blockDim.x + threadIdx.x;
    if (i < N_NODES) g_cnt[i] = 0;
}

// ---------------- convert edges + histogram dst degrees ----------------
__global__ void k_cvt_hist(const void* __restrict__ eiv) {
    int e = blockIdx.x * blockDim.x + threadIdx.x;
    if (e >= N_EDGES) return;
    int r, c;
    if (g_is64) {
        const long long* ei = (const long long*)eiv;
        r = (int)ei[e];
        c = (int)ei[N_EDGES + e];
    } else {
        const int* ei = (const int*)eiv;
        r = ei[e];
        c = ei[N_EDGES + e];
    }
    g_rowbuf[e] = r;
    g_colbuf[e] = c;
    atomicAdd(&g_cnt[c], 1);
}

// ---------------- single-block scan of g_cnt -> g_off, g_cur ----------------
__global__ __launch_bounds__(1024)
void k_scan() {
    __shared__ int sh[1024];
    const int CH = (N_NODES + 1023) / 1024;   // 49
    int tid = threadIdx.x;
    int base = tid * CH;
    int sum = 0;
    for (int j = 0; j < CH; j++) {
        int idx = base + j;
        if (idx < N_NODES) sum += g_cnt[idx];
    }
    sh[tid] = sum;
    __syncthreads();
    // Hillis-Steele inclusive scan
    for (int o = 1; o < 1024; o <<= 1) {
        int v = (tid >= o) ? sh[tid - o] : 0;
        __syncthreads();
        sh[tid] += v;
        __syncthreads();
    }
    int run = sh[tid] - sum;   // exclusive prefix of this chunk
    for (int j = 0; j < CH; j++) {
        int idx = base + j;
        if (idx < N_NODES) {
            g_off[idx] = run;
            g_cur[idx] = run;
            run += g_cnt[idx];
        }
    }
    if (tid == 1023) g_off[N_NODES] = sh[1023];
}

// ---------------- scatter edges into CSR order ----------------
__global__ void k_scatter() {
    int e = blockIdx.x * blockDim.x + threadIdx.x;
    if (e >= N_EDGES) return;
    int c = g_colbuf[e];
    int pos = atomicAdd(&g_cur[c], 1);
    g_esort[pos] = g_rowbuf[e];
}

// ---------------- Lorentz log map at origin (c=1), warp per node ----------------
__global__ void k_logmap(const float* __restrict__ x) {
    int gw = (blockIdx.x * blockDim.x + threadIdx.x) >> 5;
    int lane = threadIdx.x & 31;
    if (gw >= N_NODES) return;
    const float* xr = x + (size_t)gw * 129;
    float a0 = xr[1 + 4 * lane + 0];
    float a1 = xr[1 + 4 * lane + 1];
    float a2 = xr[1 + 4 * lane + 2];
    float a3 = xr[1 + 4 * lane + 3];
    float ss = a0 * a0 + a1 * a1 + a2 * a2 + a3 * a3;
    #pragma unroll
    for (int o = 16; o >= 1; o >>= 1) ss += __shfl_xor_sync(0xFFFFFFFFu, ss, o);
    float norm = sqrtf(ss + EPSF);
    float fac = acoshf(fmaxf(xr[0], 1.0f + EPSF)) / norm;
    float4 outv = make_float4(fac * a0, fac * a1, fac * a2, fac * a3);
    *(float4*)(g_xtan + (size_t)gw * D + 4 * lane) = outv;
}

// ---------------- 128x128x8 SGEMM, 8x8 register tiles ----------------
// C[:, blockIdx.y*128 + 0..127] = A(Mx128) @ Wsel^T (+ bias)
template<bool BIAS>
__global__ __launch_bounds__(256, 2)
void k_gemm3(const float* __restrict__ A,
             const float* __restrict__ W0, const float* __restrict__ W1,
             const float* __restrict__ W2,
             const float* __restrict__ bias, float* __restrict__ C,
             int M, int NC) {
    __shared__ float As[8][132];
    __shared__ float Bs[8][132];
    const float* B = (blockIdx.y == 0) ? W0 : ((blockIdx.y == 1) ? W1 : W2);
    int colOff = blockIdx.y * 128;
    int t = threadIdx.x;
    int rowBase = blockIdx.x * 128;
    int lr = t >> 1;                 // 0..127
    int lk = (t & 1) * 4;            // 0 or 4
    int tx = t & 15, ty = t >> 4;    // 16x16 thread grid, 8x8 outputs each
    float acc[8][8] = {};
    for (int kk = 0; kk < 128; kk += 8) {
        int r = rowBase + lr;
        float4 av = (r < M) ? *(const float4*)&A[(size_t)r * 128 + kk + lk]
                            : make_float4(0.f, 0.f, 0.f, 0.f);
        float4 bv = *(const float4*)&B[(size_t)lr * 128 + kk + lk];
        As[lk + 0][lr] = av.x; As[lk + 1][lr] = av.y;
        As[lk + 2][lr] = av.z; As[lk + 3][lr] = av.w;
        Bs[lk + 0][lr] = bv.x; Bs[lk + 1][lr] = bv.y;
        Bs[lk + 2][lr] = bv.z; Bs[lk + 3][lr] = bv.w;
        __syncthreads();
        #pragma unroll
        for (int k = 0; k < 8; k++) {
            float a[8], b[8];
            *(float4*)&a[0] = *(const float4*)&As[k][ty * 8];
            *(float4*)&a[4] = *(const float4*)&As[k][ty * 8 + 4];
            *(float4*)&b[0] = *(const float4*)&Bs[k][tx * 8];
            *(float4*)&b[4] = *(const float4*)&Bs[k][tx * 8 + 4];
            #pragma unroll
            for (int i = 0; i < 8; i++)
                #pragma unroll
                for (int j = 0; j < 8; j++)
                    acc[i][j] = fmaf(a[i], b[j], acc[i][j]);
        }
        __syncthreads();
    }
    #pragma unroll
    for (int i = 0; i < 8; i++) {
        int r = rowBase + ty * 8 + i;
        if (r >= M) continue;
        #pragma unroll
        for (int jj = 0; jj < 2; jj++) {
            int c = tx * 8 + jj * 4;
            float4 o;
            o.x = acc[i][jj * 4 + 0];
            o.y = acc[i][jj * 4 + 1];
            o.z = acc[i][jj * 4 + 2];
            o.w = acc[i][jj * 4 + 3];
            if (BIAS) {
                o.x += bias[c + 0]; o.y += bias[c + 1];
                o.z += bias[c + 2]; o.w += bias[c + 3];
            }
            *(float4*)&C[(size_t)r * NC + colOff + c] = o;
        }
    }
}

// ---------------- CSR aggregation: warp per destination node, no atomics ----
__global__ __launch_bounds__(256)
void k_agg() {
    int gw = (blockIdx.x * blockDim.x + threadIdx.x) >> 5;
    int lane = threadIdx.x & 31;
    if (gw >= N_NODES) return;
    int start = g_off[gw];
    int end   = g_off[gw + 1];
    const float* qp = g_qkv + (size_t)gw * 384;
    float4 q = *(const float4*)(qp + 4 * lane);
    float4 acc = make_float4(0.f, 0.f, 0.f, 0.f);
    float dsum = 0.f;
    for (int i = start; i < end; i++) {
        int src = g_esort[i];
        const float* bp = g_qkv + (size_t)src * 384;
        float4 k4 = *(const float4*)(bp + 128 + 4 * lane);
        float p = q.x * k4.x + q.y * k4.y + q.z * k4.z + q.w * k4.w;
        p += __shfl_xor_sync(0xFFFFFFFFu, p, 4);
        p += __shfl_xor_sync(0xFFFFFFFFu, p, 2);
        p += __shfl_xor_sync(0xFFFFFFFFu, p, 1);
        float ev = __expf(p * SCALEF);   // softmax shift cancels exactly in agg/denom
        float4 v4 = *(const float4*)(bp + 256 + 4 * lane);
        dsum += ev;
        acc.x = fmaf(ev, v4.x, acc.x);
        acc.y = fmaf(ev, v4.y, acc.y);
        acc.z = fmaf(ev, v4.z, acc.z);
        acc.w = fmaf(ev, v4.w, acc.w);
    }
    float inv = (dsum > 0.f) ? (1.0f / dsum) : 0.f;
    float4 o = make_float4(acc.x * inv, acc.y * inv, acc.z * inv, acc.w * inv);
    *(float4*)(g_agg + (size_t)gw * 128 + 4 * lane) = o;
}

// ---------------- Lorentz exp map at origin (c=1), warp per node ----------------
__global__ void k_expmap(float* __restrict__ out) {
    int gw = (blockIdx.x * blockDim.x + threadIdx.x) >> 5;
    int lane = threadIdx.x & 31;
    if (gw >= N_NODES) return;
    const float* vr = g_otan + (size_t)gw * D;
    float4 v = *(const float4*)(vr + 4 * lane);
    float ss = v.x * v.x + v.y * v.y + v.z * v.z + v.w * v.w;
    #pragma unroll
    for (int o = 16; o >= 1; o >>= 1) ss += __shfl_xor_sync(0xFFFFFFFFu, ss, o);
    float r = sqrtf(ss + EPSF);
    float x0 = coshf(r);
    float fac = sinhf(r) / r;
    float* orow = out + (size_t)gw * 129;
    if (lane == 0) orow[0] = x0;
    orow[1 + 4 * lane + 0] = fac * v.x;
    orow[1 + 4 * lane + 1] = fac * v.y;
    orow[1 + 4 * lane + 2] = fac * v.z;
    orow[1 + 4 * lane + 3] = fac * v.w;
}

// ---------------- launch ----------------
extern "C" void kernel_launch(void* const* d_in, const int* in_sizes, int n_in,
                              void* d_out, int out_size) {
    const float* x  = (const float*)d_in[0];
    const void*  ei = (const void*)d_in[1];
    const float* Wq = (const float*)d_in[2];
    const float* Wk = (const float*)d_in[3];
    const float* Wv = (const float*)d_in[4];
    const float* Wo = (const float*)d_in[5];
    const float* bo = (const float*)d_in[6];
    float* out      = (float*)d_out;
    (void)in_sizes; (void)n_in; (void)out_size;

    // real device addresses of __device__ globals (ATS pitfall!)
    float *xtan, *qkv, *agg, *otan;
    cudaGetSymbolAddress((void**)&xtan, g_xtan);
    cudaGetSymbolAddress((void**)&qkv,  g_qkv);
    cudaGetSymbolAddress((void**)&agg,  g_agg);
    cudaGetSymbolAddress((void**)&otan, g_otan);

    // CSR build
    k_detect_edges<<<1, 32>>>((const unsigned int*)ei);
    k_zero_cnt<<<(N_NODES + 255) / 256, 256>>>();
    k_cvt_hist<<<(N_EDGES + 255) / 256, 256>>>(ei);
    k_scan<<<1, 1024>>>();
    k_scatter<<<(N_EDGES + 255) / 256, 256>>>();
    // log map
    k_logmap<<<(N_NODES * 32 + 255) / 256, 256>>>(x);
    // fused QKV projection: grid.y selects Wq/Wk/Wv, column offset y*128
    {
        dim3 grid((N_NODES + 127) / 128, 3);
        k_gemm3<false><<<grid, 256>>>(xtan, Wq, Wk, Wv, nullptr, qkv, N_NODES, 384);
    }
    // attention aggregation (no atomics, pre-normalized)
    k_agg<<<(N_NODES * 32 + 255) / 256, 256>>>();
    // output projection: out_tan = agg @ Wo^T + bo
    {
        dim3 grid((N_NODES + 127) / 128, 1);
        k_gemm3<true><<<grid, 256>>>(agg, Wo, Wo, Wo, bo, otan, N_NODES, 128);
    }
    k_expmap<<<(N_NODES * 32 + 255) / 256, 256>>>(out);
}

// round 9
// speedup vs baseline: 1.7761x; 1.2316x over previous
#include <cuda_runtime.h>
#include <math.h>

#define N_NODES 50000
#define N_EDGES 800000
#define D 128
#define HEADS 4
#define SCALEF 0.17677669529663687f   // 32^-0.5
#define EPSF 1e-7f
#define SCAN_BLOCKS ((N_NODES + 255) / 256)   // 196

// ---------------- static device scratch ----------------
__device__ float g_xtan[(size_t)N_NODES * D];
__device__ float g_qkv[(size_t)N_NODES * 3 * D];   // per node: Q|K|V
__device__ float g_agg[(size_t)N_NODES * D];       // attention output, pre-divided by denom
__device__ float g_otan[(size_t)N_NODES * D];
__device__ int   g_rowbuf[N_EDGES];
__device__ int   g_colbuf[N_EDGES];
__device__ int   g_cnt[N_NODES];                   // per-dst degree
__device__ int   g_off[N_NODES + 1];               // CSR offsets
__device__ int   g_cur[N_NODES];                   // scatter cursors
__device__ int   g_esort[N_EDGES];                 // src node ids grouped by dst
__device__ int   g_bsum[SCAN_BLOCKS];              // per-block sums
__device__ int   g_boff[SCAN_BLOCKS];              // exclusive block offsets
__device__ int   g_is64;

// ---------------- edge dtype detect ----------------
__global__ void k_detect_edges(const unsigned int* __restrict__ w) {
    if (threadIdx.x == 0 && blockIdx.x == 0) {
        int all0 = 1;
        #pragma unroll
        for (int i = 0; i < 32; i++) all0 &= (w[2 * i + 1] == 0u);
        g_is64 = all0;
    }
}

// ---------------- zero histogram ----------------
__global__ void k_zero_cnt() {
    int i = blockIdx.x * blockDim.x + threadIdx.x;
    if (i < N_NODES) g_cnt[i] = 0;
}

// ---------------- convert edges + histogram dst degrees ----------------
__global__ void k_cvt_hist(const void* __restrict__ eiv) {
    int e = blockIdx.x * blockDim.x + threadIdx.x;
    if (e >= N_EDGES) return;
    int r, c;
    if (g_is64) {
        const long long* ei = (const long long*)eiv;
        r = (int)ei[e];
        c = (int)ei[N_EDGES + e];
    } else {
        const int* ei = (const int*)eiv;
        r = ei[e];
        c = ei[N_EDGES + e];
    }
    g_rowbuf[e] = r;
    g_colbuf[e] = c;
    atomicAdd(&g_cnt[c], 1);
}

// ---------------- parallel scan, phase A: block scans ----------------
__global__ __launch_bounds__(256)
void k_scanA() {
    int tid = threadIdx.x;
    int i = blockIdx.x * 256 + tid;
    int v = (i < N_NODES) ? g_cnt[i] : 0;
    int lane = tid & 31, wid = tid >> 5;
    // warp inclusive scan
    int s = v;
    #pragma unroll
    for (int o = 1; o < 32; o <<= 1) {
        int t = __shfl_up_sync(0xFFFFFFFFu, s, o);
        if (lane >= o) s += t;
    }
    __shared__ int wsum[8];
    if (lane == 31) wsum[wid] = s;
    __syncthreads();
    if (wid == 0) {
        int ws = (lane < 8) ? wsum[lane] : 0;
        #pragma unroll
        for (int o = 1; o < 8; o <<= 1) {
            int t = __shfl_up_sync(0xFFFFFFFFu, ws, o);
            if (lane >= o) ws += t;
        }
        if (lane < 8) wsum[lane] = ws;   // inclusive warp-sum scan
    }
    __syncthreads();
    int inc = s + ((wid > 0) ? wsum[wid - 1] : 0);
    if (i < N_NODES) g_off[i] = inc - v;        // in-block exclusive prefix
    if (tid == 255) g_bsum[blockIdx.x] = inc;   // block total
}

// ---------------- phase B: scan block sums (1 block) ----------------
__global__ __launch_bounds__(256)
void k_scanB() {
    int tid = threadIdx.x;
    int v = (tid < SCAN_BLOCKS) ? g_bsum[tid] : 0;
    int lane = tid & 31, wid = tid >> 5;
    int s = v;
    #pragma unroll
    for (int o = 1; o < 32; o <<= 1) {
        int t = __shfl_up_sync(0xFFFFFFFFu, s, o);
        if (lane >= o) s += t;
    }
    __shared__ int wsum[8];
    if (lane == 31) wsum[wid] = s;
    __syncthreads();
    if (wid == 0) {
        int ws = (lane < 8) ? wsum[lane] : 0;
        #pragma unroll
        for (int o = 1; o < 8; o <<= 1) {
            int t = __shfl_up_sync(0xFFFFFFFFu, ws, o);
            if (lane >= o) ws += t;
        }
        if (lane < 8) wsum[lane] = ws;
    }
    __syncthreads();
    int inc = s + ((wid > 0) ? wsum[wid - 1] : 0);
    if (tid < SCAN_BLOCKS) g_boff[tid] = inc - v;   // exclusive block offset
}

// ---------------- phase C: finalize offsets + cursors ----------------
__global__ __launch_bounds__(256)
void k_scanC() {
    int i = blockIdx.x * 256 + threadIdx.x;
    if (i < N_NODES) {
        int o = g_off[i] + g_boff[blockIdx.x];
        g_off[i] = o;
        g_cur[i] = o;
    }
    if (i == 0) g_off[N_NODES] = N_EDGES;
}

// ---------------- scatter edges into CSR order ----------------
__global__ void k_scatter() {
    int e = blockIdx.x * blockDim.x + threadIdx.x;
    if (e >= N_EDGES) return;
    int c = g_colbuf[e];
    int pos = atomicAdd(&g_cur[c], 1);
    g_esort[pos] = g_rowbuf[e];
}

// ---------------- Lorentz log map at origin (c=1), warp per node ----------------
__global__ void k_logmap(const float* __restrict__ x) {
    int gw = (blockIdx.x * blockDim.x + threadIdx.x) >> 5;
    int lane = threadIdx.x & 31;
    if (gw >= N_NODES) return;
    const float* xr = x + (size_t)gw * 129;
    float a0 = xr[1 + 4 * lane + 0];
    float a1 = xr[1 + 4 * lane + 1];
    float a2 = xr[1 + 4 * lane + 2];
    float a3 = xr[1 + 4 * lane + 3];
    float ss = a0 * a0 + a1 * a1 + a2 * a2 + a3 * a3;
    #pragma unroll
    for (int o = 16; o >= 1; o >>= 1) ss += __shfl_xor_sync(0xFFFFFFFFu, ss, o);
    float norm = sqrtf(ss + EPSF);
    float fac = acoshf(fmaxf(xr[0], 1.0f + EPSF)) / norm;
    float4 outv = make_float4(fac * a0, fac * a1, fac * a2, fac * a3);
    *(float4*)(g_xtan + (size_t)gw * D + 4 * lane) = outv;
}

// ---------------- 128x128x8 SGEMM, 8x8 register tiles ----------------
template<bool BIAS>
__global__ __launch_bounds__(256, 2)
void k_gemm3(const float* __restrict__ A,
             const float* __restrict__ W0, const float* __restrict__ W1,
             const float* __restrict__ W2,
             const float* __restrict__ bias, float* __restrict__ C,
             int M, int NC) {
    __shared__ float As[8][132];
    __shared__ float Bs[8][132];
    const float* B = (blockIdx.y == 0) ? W0 : ((blockIdx.y == 1) ? W1 : W2);
    int colOff = blockIdx.y * 128;
    int t = threadIdx.x;
    int rowBase = blockIdx.x * 128;
    int lr = t >> 1;
    int lk = (t & 1) * 4;
    int tx = t & 15, ty = t >> 4;
    float acc[8][8] = {};
    for (int kk = 0; kk < 128; kk += 8) {
        int r = rowBase + lr;
        float4 av = (r < M) ? *(const float4*)&A[(size_t)r * 128 + kk + lk]
                            : make_float4(0.f, 0.f, 0.f, 0.f);
        float4 bv = *(const float4*)&B[(size_t)lr * 128 + kk + lk];
        As[lk + 0][lr] = av.x; As[lk + 1][lr] = av.y;
        As[lk + 2][lr] = av.z; As[lk + 3][lr] = av.w;
        Bs[lk + 0][lr] = bv.x; Bs[lk + 1][lr] = bv.y;
        Bs[lk + 2][lr] = bv.z; Bs[lk + 3][lr] = bv.w;
        __syncthreads();
        #pragma unroll
        for (int k = 0; k < 8; k++) {
            float a[8], b[8];
            *(float4*)&a[0] = *(const float4*)&As[k][ty * 8];
            *(float4*)&a[4] = *(const float4*)&As[k][ty * 8 + 4];
            *(float4*)&b[0] = *(const float4*)&Bs[k][tx * 8];
            *(float4*)&b[4] = *(const float4*)&Bs[k][tx * 8 + 4];
            #pragma unroll
            for (int i = 0; i < 8; i++)
                #pragma unroll
                for (int j = 0; j < 8; j++)
                    acc[i][j] = fmaf(a[i], b[j], acc[i][j]);
        }
        __syncthreads();
    }
    #pragma unroll
    for (int i = 0; i < 8; i++) {
        int r = rowBase + ty * 8 + i;
        if (r >= M) continue;
        #pragma unroll
        for (int jj = 0; jj < 2; jj++) {
            int c = tx * 8 + jj * 4;
            float4 o;
            o.x = acc[i][jj * 4 + 0];
            o.y = acc[i][jj * 4 + 1];
            o.z = acc[i][jj * 4 + 2];
            o.w = acc[i][jj * 4 + 3];
            if (BIAS) {
                o.x += bias[c + 0]; o.y += bias[c + 1];
                o.z += bias[c + 2]; o.w += bias[c + 3];
            }
            *(float4*)&C[(size_t)r * NC + colOff + c] = o;
        }
    }
}

// ---------------- CSR aggregation: warp per destination node, no atomics ----
__global__ __launch_bounds__(256)
void k_agg() {
    int gw = (blockIdx.x * blockDim.x + threadIdx.x) >> 5;
    int lane = threadIdx.x & 31;
    if (gw >= N_NODES) return;
    int start = g_off[gw];
    int end   = g_off[gw + 1];
    const float* qp = g_qkv + (size_t)gw * 384;
    float4 q = *(const float4*)(qp + 4 * lane);
    float4 acc = make_float4(0.f, 0.f, 0.f, 0.f);
    float dsum = 0.f;
    for (int i = start; i < end; i++) {
        int src = g_esort[i];
        const float* bp = g_qkv + (size_t)src * 384;
        float4 k4 = *(const float4*)(bp + 128 + 4 * lane);
        float p = q.x * k4.x + q.y * k4.y + q.z * k4.z + q.w * k4.w;
        p += __shfl_xor_sync(0xFFFFFFFFu, p, 4);
        p += __shfl_xor_sync(0xFFFFFFFFu, p, 2);
        p += __shfl_xor_sync(0xFFFFFFFFu, p, 1);
        float ev = __expf(p * SCALEF);
        float4 v4 = *(const float4*)(bp + 256 + 4 * lane);
        dsum += ev;
        acc.x = fmaf(ev, v4.x, acc.x);
        acc.y = fmaf(ev, v4.y, acc.y);
        acc.z = fmaf(ev, v4.z, acc.z);
        acc.w = fmaf(ev, v4.w, acc.w);
    }
    float inv = (dsum > 0.f) ? (1.0f / dsum) : 0.f;
    float4 o = make_float4(acc.x * inv, acc.y * inv, acc.z * inv, acc.w * inv);
    *(float4*)(g_agg + (size_t)gw * 128 + 4 * lane) = o;
}

// ---------------- Lorentz exp map at origin (c=1), warp per node ----------------
__global__ void k_expmap(float* __restrict__ out) {
    int gw = (blockIdx.x * blockDim.x + threadIdx.x) >> 5;
    int lane = threadIdx.x & 31;
    if (gw >= N_NODES) return;
    const float* vr = g_otan + (size_t)gw * D;
    float4 v = *(const float4*)(vr + 4 * lane);
    float ss = v.x * v.x + v.y * v.y + v.z * v.z + v.w * v.w;
    #pragma unroll
    for (int o = 16; o >= 1; o >>= 1) ss += __shfl_xor_sync(0xFFFFFFFFu, ss, o);
    float r = sqrtf(ss + EPSF);
    float x0 = coshf(r);
    float fac = sinhf(r) / r;
    float* orow = out + (size_t)gw * 129;
    if (lane == 0) orow[0] = x0;
    orow[1 + 4 * lane + 0] = fac * v.x;
    orow[1 + 4 * lane + 1] = fac * v.y;
    orow[1 + 4 * lane + 2] = fac * v.z;
    orow[1 + 4 * lane + 3] = fac * v.w;
}

// ---------------- launch ----------------
extern "C" void kernel_launch(void* const* d_in, const int* in_sizes, int n_in,
                              void* d_out, int out_size) {
    const float* x  = (const float*)d_in[0];
    const void*  ei = (const void*)d_in[1];
    const float* Wq = (const float*)d_in[2];
    const float* Wk = (const float*)d_in[3];
    const float* Wv = (const float*)d_in[4];
    const float* Wo = (const float*)d_in[5];
    const float* bo = (const float*)d_in[6];
    float* out      = (float*)d_out;
    (void)in_sizes; (void)n_in; (void)out_size;

    // real device addresses of __device__ globals (ATS pitfall!)
    float *xtan, *qkv, *agg, *otan;
    cudaGetSymbolAddress((void**)&xtan, g_xtan);
    cudaGetSymbolAddress((void**)&qkv,  g_qkv);
    cudaGetSymbolAddress((void**)&agg,  g_agg);
    cudaGetSymbolAddress((void**)&otan, g_otan);

    // CSR build
    k_detect_edges<<<1, 32>>>((const unsigned int*)ei);
    k_zero_cnt<<<(N_NODES + 255) / 256, 256>>>();
    k_cvt_hist<<<(N_EDGES + 255) / 256, 256>>>(ei);
    k_scanA<<<SCAN_BLOCKS, 256>>>();
    k_scanB<<<1, 256>>>();
    k_scanC<<<SCAN_BLOCKS, 256>>>();
    k_scatter<<<(N_EDGES + 255) / 256, 256>>>();
    // log map
    k_logmap<<<(N_NODES * 32 + 255) / 256, 256>>>(x);
    // fused QKV projection
    {
        dim3 grid((N_NODES + 127) / 128, 3);
        k_gemm3<false><<<grid, 256>>>(xtan, Wq, Wk, Wv, nullptr, qkv, N_NODES, 384);
    }
    // attention aggregation (no atomics, pre-normalized)
    k_agg<<<(N_NODES * 32 + 255) / 256, 256>>>();
    // output projection
    {
        dim3 grid((N_NODES + 127) / 128, 1);
        k_gemm3<true><<<grid, 256>>>(agg, Wo, Wo, Wo, bo, otan, N_NODES, 128);
    }
    k_expmap<<<(N_NODES * 32 + 255) / 256, 256>>>(out);
}

// round 10
// speedup vs baseline: 1.9359x; 1.0900x over previous
#include <cuda_runtime.h>
#include <cuda_fp16.h>
#include <math.h>

#define N_NODES 50000
#define N_EDGES 800000
#define D 128
#define HEADS 4
#define SCALEF 0.17677669529663687f   // 32^-0.5
#define EPSF 1e-7f
#define SCAN_BLOCKS ((N_NODES + 255) / 256)   // 196

// ---------------- static device scratch ----------------
__device__ float  g_xtan[(size_t)N_NODES * D];
__device__ float  g_q[(size_t)N_NODES * D];          // Q fp32
__device__ __half g_kvh[(size_t)N_NODES * 2 * D];    // per node: K(128) | V(128) fp16
__device__ float  g_agg[(size_t)N_NODES * D];        // attention out, pre-normalized
__device__ float  g_otan[(size_t)N_NODES * D];
__device__ int    g_rowbuf[N_EDGES];
__device__ int    g_colbuf[N_EDGES];
__device__ int    g_cnt[N_NODES];
__device__ int    g_off[N_NODES + 1];
__device__ int    g_cur[N_NODES];
__device__ int    g_esort[N_EDGES];
__device__ int    g_bsum[SCAN_BLOCKS];
__device__ int    g_boff[SCAN_BLOCKS];
__device__ int    g_is64;

// ---------------- edge dtype detect ----------------
__global__ void k_detect_edges(const unsigned int* __restrict__ w) {
    if (threadIdx.x == 0 && blockIdx.x == 0) {
        int all0 = 1;
        #pragma unroll
        for (int i = 0; i < 32; i++) all0 &= (w[2 * i + 1] == 0u);
        g_is64 = all0;
    }
}

__global__ void k_zero_cnt() {
    int i = blockIdx.x * blockDim.x + threadIdx.x;
    if (i < N_NODES) g_cnt[i] = 0;
}

__global__ void k_cvt_hist(const void* __restrict__ eiv) {
    int e = blockIdx.x * blockDim.x + threadIdx.x;
    if (e >= N_EDGES) return;
    int r, c;
    if (g_is64) {
        const long long* ei = (const long long*)eiv;
        r = (int)ei[e];
        c = (int)ei[N_EDGES + e];
    } else {
        const int* ei = (const int*)eiv;
        r = ei[e];
        c = ei[N_EDGES + e];
    }
    g_rowbuf[e] = r;
    g_colbuf[e] = c;
    atomicAdd(&g_cnt[c], 1);
}

// ---------------- parallel scan (3 phases) ----------------
__global__ __launch_bounds__(256)
void k_scanA() {
    int tid = threadIdx.x;
    int i = blockIdx.x * 256 + tid;
    int v = (i < N_NODES) ? g_cnt[i] : 0;
    int lane = tid & 31, wid = tid >> 5;
    int s = v;
    #pragma unroll
    for (int o = 1; o < 32; o <<= 1) {
        int t = __shfl_up_sync(0xFFFFFFFFu, s, o);
        if (lane >= o) s += t;
    }
    __shared__ int wsum[8];
    if (lane == 31) wsum[wid] = s;
    __syncthreads();
    if (wid == 0) {
        int ws = (lane < 8) ? wsum[lane] : 0;
        #pragma unroll
        for (int o = 1; o < 8; o <<= 1) {
            int t = __shfl_up_sync(0xFFFFFFFFu, ws, o);
            if (lane >= o) ws += t;
        }
        if (lane < 8) wsum[lane] = ws;
    }
    __syncthreads();
    int inc = s + ((wid > 0) ? wsum[wid - 1] : 0);
    if (i < N_NODES) g_off[i] = inc - v;
    if (tid == 255) g_bsum[blockIdx.x] = inc;
}

__global__ __launch_bounds__(256)
void k_scanB() {
    int tid = threadIdx.x;
    int v = (tid < SCAN_BLOCKS) ? g_bsum[tid] : 0;
    int lane = tid & 31, wid = tid >> 5;
    int s = v;
    #pragma unroll
    for (int o = 1; o < 32; o <<= 1) {
        int t = __shfl_up_sync(0xFFFFFFFFu, s, o);
        if (lane >= o) s += t;
    }
    __shared__ int wsum[8];
    if (lane == 31) wsum[wid] = s;
    __syncthreads();
    if (wid == 0) {
        int ws = (lane < 8) ? wsum[lane] : 0;
        #pragma unroll
        for (int o = 1; o < 8; o <<= 1) {
            int t = __shfl_up_sync(0xFFFFFFFFu, ws, o);
            if (lane >= o) ws += t;
        }
        if (lane < 8) wsum[lane] = ws;
    }
    __syncthreads();
    int inc = s + ((wid > 0) ? wsum[wid - 1] : 0);
    if (tid < SCAN_BLOCKS) g_boff[tid] = inc - v;
}

__global__ __launch_bounds__(256)
void k_scanC() {
    int i = blockIdx.x * 256 + threadIdx.x;
    if (i < N_NODES) {
        int o = g_off[i] + g_boff[blockIdx.x];
        g_off[i] = o;
        g_cur[i] = o;
    }
    if (i == 0) g_off[N_NODES] = N_EDGES;
}

__global__ void k_scatter() {
    int e = blockIdx.x * blockDim.x + threadIdx.x;
    if (e >= N_EDGES) return;
    int c = g_colbuf[e];
    int pos = atomicAdd(&g_cur[c], 1);
    g_esort[pos] = g_rowbuf[e];
}

// ---------------- Lorentz log map, warp per node ----------------
__global__ void k_logmap(const float* __restrict__ x) {
    int gw = (blockIdx.x * blockDim.x + threadIdx.x) >> 5;
    int lane = threadIdx.x & 31;
    if (gw >= N_NODES) return;
    const float* xr = x + (size_t)gw * 129;
    float a0 = xr[1 + 4 * lane + 0];
    float a1 = xr[1 + 4 * lane + 1];
    float a2 = xr[1 + 4 * lane + 2];
    float a3 = xr[1 + 4 * lane + 3];
    float ss = a0 * a0 + a1 * a1 + a2 * a2 + a3 * a3;
    #pragma unroll
    for (int o = 16; o >= 1; o >>= 1) ss += __shfl_xor_sync(0xFFFFFFFFu, ss, o);
    float norm = sqrtf(ss + EPSF);
    float fac = acoshf(fmaxf(xr[0], 1.0f + EPSF)) / norm;
    float4 outv = make_float4(fac * a0, fac * a1, fac * a2, fac * a3);
    *(float4*)(g_xtan + (size_t)gw * D + 4 * lane) = outv;
}

// ---------------- QKV GEMM 128x128x8, Q->fp32, K/V->fp16 ----------------
__global__ __launch_bounds__(256, 2)
void k_gemmQKV(const float* __restrict__ A,
               const float* __restrict__ Wq, const float* __restrict__ Wk,
               const float* __restrict__ Wv,
               float* __restrict__ Q, __half* __restrict__ KV, int M) {
    __shared__ float As[8][132];
    __shared__ float Bs[8][132];
    int sel = blockIdx.y;
    const float* B = (sel == 0) ? Wq : ((sel == 1) ? Wk : Wv);
    int t = threadIdx.x;
    int rowBase = blockIdx.x * 128;
    int lr = t >> 1;
    int lk = (t & 1) * 4;
    int tx = t & 15, ty = t >> 4;
    float acc[8][8] = {};
    for (int kk = 0; kk < 128; kk += 8) {
        int r = rowBase + lr;
        float4 av = (r < M) ? *(const float4*)&A[(size_t)r * 128 + kk + lk]
                            : make_float4(0.f, 0.f, 0.f, 0.f);
        float4 bv = *(const float4*)&B[(size_t)lr * 128 + kk + lk];
        As[lk + 0][lr] = av.x; As[lk + 1][lr] = av.y;
        As[lk + 2][lr] = av.z; As[lk + 3][lr] = av.w;
        Bs[lk + 0][lr] = bv.x; Bs[lk + 1][lr] = bv.y;
        Bs[lk + 2][lr] = bv.z; Bs[lk + 3][lr] = bv.w;
        __syncthreads();
        #pragma unroll
        for (int k = 0; k < 8; k++) {
            float a[8], b[8];
            *(float4*)&a[0] = *(const float4*)&As[k][ty * 8];
            *(float4*)&a[4] = *(const float4*)&As[k][ty * 8 + 4];
            *(float4*)&b[0] = *(const float4*)&Bs[k][tx * 8];
            *(float4*)&b[4] = *(const float4*)&Bs[k][tx * 8 + 4];
            #pragma unroll
            for (int i = 0; i < 8; i++)
                #pragma unroll
                for (int j = 0; j < 8; j++)
                    acc[i][j] = fmaf(a[i], b[j], acc[i][j]);
        }
        __syncthreads();
    }
    if (sel == 0) {
        #pragma unroll
        for (int i = 0; i < 8; i++) {
            int r = rowBase + ty * 8 + i;
            if (r >= M) continue;
            #pragma unroll
            for (int jj = 0; jj < 2; jj++) {
                int c = tx * 8 + jj * 4;
                float4 o = make_float4(acc[i][jj * 4 + 0], acc[i][jj * 4 + 1],
                                       acc[i][jj * 4 + 2], acc[i][jj * 4 + 3]);
                *(float4*)&Q[(size_t)r * 128 + c] = o;
            }
        }
    } else {
        int off = (sel - 1) * 128;   // K at 0, V at 128 within the 256-half row
        #pragma unroll
        for (int i = 0; i < 8; i++) {
            int r = rowBase + ty * 8 + i;
            if (r >= M) continue;
            #pragma unroll
            for (int jj = 0; jj < 2; jj++) {
                int c = tx * 8 + jj * 4;
                __half2 h0 = __float22half2_rn(make_float2(acc[i][jj * 4 + 0], acc[i][jj * 4 + 1]));
                __half2 h1 = __float22half2_rn(make_float2(acc[i][jj * 4 + 2], acc[i][jj * 4 + 3]));
                uint2 u;
                u.x = *reinterpret_cast<unsigned int*>(&h0);
                u.y = *reinterpret_cast<unsigned int*>(&h1);
                *(uint2*)&KV[(size_t)r * 256 + off + c] = u;
            }
        }
    }
}

// ---------------- fp16 gather helper ----------------
__device__ __forceinline__ float4 ld4h(const __half* p) {
    uint2 u = *(const uint2*)p;
    __half2 h0 = *reinterpret_cast<__half2*>(&u.x);
    __half2 h1 = *reinterpret_cast<__half2*>(&u.y);
    float2 f0 = __half22float2(h0);
    float2 f1 = __half22float2(h1);
    return make_float4(f0.x, f0.y, f1.x, f1.y);
}

// ---------------- CSR aggregation: warp per dst, fp16 K/V, 2-way unroll ----
__global__ __launch_bounds__(256)
void k_agg() {
    int gw = (blockIdx.x * blockDim.x + threadIdx.x) >> 5;
    int lane = threadIdx.x & 31;
    if (gw >= N_NODES) return;
    int start = g_off[gw];
    int end   = g_off[gw + 1];
    float4 q = *(const float4*)(g_q + (size_t)gw * 128 + 4 * lane);
    float4 acc = make_float4(0.f, 0.f, 0.f, 0.f);
    float dsum = 0.f;
    int i = start;
    for (; i + 2 <= end; i += 2) {
        int s0 = g_esort[i];
        int s1 = g_esort[i + 1];
        const __half* b0 = g_kvh + (size_t)s0 * 256;
        const __half* b1 = g_kvh + (size_t)s1 * 256;
        float4 k0 = ld4h(b0 + 4 * lane);
        float4 k1 = ld4h(b1 + 4 * lane);
        float p0 = q.x * k0.x + q.y * k0.y + q.z * k0.z + q.w * k0.w;
        float p1 = q.x * k1.x + q.y * k1.y + q.z * k1.z + q.w * k1.w;
        p0 += __shfl_xor_sync(0xFFFFFFFFu, p0, 4);
        p1 += __shfl_xor_sync(0xFFFFFFFFu, p1, 4);
        p0 += __shfl_xor_sync(0xFFFFFFFFu, p0, 2);
        p1 += __shfl_xor_sync(0xFFFFFFFFu, p1, 2);
        p0 += __shfl_xor_sync(0xFFFFFFFFu, p0, 1);
        p1 += __shfl_xor_sync(0xFFFFFFFFu, p1, 1);
        float e0 = __expf(p0 * SCALEF);
        float e1 = __expf(p1 * SCALEF);
        float4 v0 = ld4h(b0 + 128 + 4 * lane);
        float4 v1 = ld4h(b1 + 128 + 4 * lane);
        dsum += e0 + e1;
        acc.x = fmaf(e0, v0.x, fmaf(e1, v1.x, acc.x));
        acc.y = fmaf(e0, v0.y, fmaf(e1, v1.y, acc.y));
        acc.z = fmaf(e0, v0.z, fmaf(e1, v1.z, acc.z));
        acc.w = fmaf(e0, v0.w, fmaf(e1, v1.w, acc.w));
    }
    if (i < end) {
        int s0 = g_esort[i];
        const __half* b0 = g_kvh + (size_t)s0 * 256;
        float4 k0 = ld4h(b0 + 4 * lane);
        float p0 = q.x * k0.x + q.y * k0.y + q.z * k0.z + q.w * k0.w;
        p0 += __shfl_xor_sync(0xFFFFFFFFu, p0, 4);
        p0 += __shfl_xor_sync(0xFFFFFFFFu, p0, 2);
        p0 += __shfl_xor_sync(0xFFFFFFFFu, p0, 1);
        float e0 = __expf(p0 * SCALEF);
        float4 v0 = ld4h(b0 + 128 + 4 * lane);
        dsum += e0;
        acc.x = fmaf(e0, v0.x, acc.x);
        acc.y = fmaf(e0, v0.y, acc.y);
        acc.z = fmaf(e0, v0.z, acc.z);
        acc.w = fmaf(e0, v0.w, acc.w);
    }
    float inv = (dsum > 0.f) ? (1.0f / dsum) : 0.f;
    float4 o = make_float4(acc.x * inv, acc.y * inv, acc.z * inv, acc.w * inv);
    *(float4*)(g_agg + (size_t)gw * 128 + 4 * lane) = o;
}

// ---------------- output GEMM 128x128x8 fp32 + bias ----------------
__global__ __launch_bounds__(256, 2)
void k_gemmO(const float* __restrict__ A, const float* __restrict__ B,
             const float* __restrict__ bias, float* __restrict__ C, int M) {
    __shared__ float As[8][132];
    __shared__ float Bs[8][132];
    int t = threadIdx.x;
    int rowBase = blockIdx.x * 128;
    int lr = t >> 1;
    int lk = (t & 1) * 4;
    int tx = t & 15, ty = t >> 4;
    float acc[8][8] = {};
    for (int kk = 0; kk < 128; kk += 8) {
        int r = rowBase + lr;
        float4 av = (r < M) ? *(const float4*)&A[(size_t)r * 128 + kk + lk]
                            : make_float4(0.f, 0.f, 0.f, 0.f);
        float4 bv = *(const float4*)&B[(size_t)lr * 128 + kk + lk];
        As[lk + 0][lr] = av.x; As[lk + 1][lr] = av.y;
        As[lk + 2][lr] = av.z; As[lk + 3][lr] = av.w;
        Bs[lk + 0][lr] = bv.x; Bs[lk + 1][lr] = bv.y;
        Bs[lk + 2][lr] = bv.z; Bs[lk + 3][lr] = bv.w;
        __syncthreads();
        #pragma unroll
        for (int k = 0; k < 8; k++) {
            float a[8], b[8];
            *(float4*)&a[0] = *(const float4*)&As[k][ty * 8];
            *(float4*)&a[4] = *(const float4*)&As[k][ty * 8 + 4];
            *(float4*)&b[0] = *(const float4*)&Bs[k][tx * 8];
            *(float4*)&b[4] = *(const float4*)&Bs[k][tx * 8 + 4];
            #pragma unroll
            for (int i = 0; i < 8; i++)
                #pragma unroll
                for (int j = 0; j < 8; j++)
                    acc[i][j] = fmaf(a[i], b[j], acc[i][j]);
        }
        __syncthreads();
    }
    #pragma unroll
    for (int i = 0; i < 8; i++) {
        int r = rowBase + ty * 8 + i;
        if (r >= M) continue;
        #pragma unroll
        for (int jj = 0; jj < 2; jj++) {
            int c = tx * 8 + jj * 4;
            float4 o = make_float4(acc[i][jj * 4 + 0] + bias[c + 0],
                                   acc[i][jj * 4 + 1] + bias[c + 1],
                                   acc[i][jj * 4 + 2] + bias[c + 2],
                                   acc[i][jj * 4 + 3] + bias[c + 3]);
            *(float4*)&C[(size_t)r * 128 + c] = o;
        }
    }
}

// ---------------- Lorentz exp map, warp per node ----------------
__global__ void k_expmap(float* __restrict__ out) {
    int gw = (blockIdx.x * blockDim.x + threadIdx.x) >> 5;
    int lane = threadIdx.x & 31;
    if (gw >= N_NODES) return;
    const float* vr = g_otan + (size_t)gw * D;
    float4 v = *(const float4*)(vr + 4 * lane);
    float ss = v.x * v.x + v.y * v.y + v.z * v.z + v.w * v.w;
    #pragma unroll
    for (int o = 16; o >= 1; o >>= 1) ss += __shfl_xor_sync(0xFFFFFFFFu, ss, o);
    float r = sqrtf(ss + EPSF);
    float x0 = coshf(r);
    float fac = sinhf(r) / r;
    float* orow = out + (size_t)gw * 129;
    if (lane == 0) orow[0] = x0;
    orow[1 + 4 * lane + 0] = fac * v.x;
    orow[1 + 4 * lane + 1] = fac * v.y;
    orow[1 + 4 * lane + 2] = fac * v.z;
    orow[1 + 4 * lane + 3] = fac * v.w;
}

// ---------------- launch ----------------
extern "C" void kernel_launch(void* const* d_in, const int* in_sizes, int n_in,
                              void* d_out, int out_size) {
    const float* x  = (const float*)d_in[0];
    const void*  ei = (const void*)d_in[1];
    const float* Wq = (const float*)d_in[2];
    const float* Wk = (const float*)d_in[3];
    const float* Wv = (const float*)d_in[4];
    const float* Wo = (const float*)d_in[5];
    const float* bo = (const float*)d_in[6];
    float* out      = (float*)d_out;
    (void)in_sizes; (void)n_in; (void)out_size;

    // real device addresses of __device__ globals (ATS pitfall!)
    float *xtan, *q, *agg, *otan;
    __half* kvh;
    cudaGetSymbolAddress((void**)&xtan, g_xtan);
    cudaGetSymbolAddress((void**)&q,    g_q);
    cudaGetSymbolAddress((void**)&kvh,  g_kvh);
    cudaGetSymbolAddress((void**)&agg,  g_agg);
    cudaGetSymbolAddress((void**)&otan, g_otan);

    // CSR build
    k_detect_edges<<<1, 32>>>((const unsigned int*)ei);
    k_zero_cnt<<<(N_NODES + 255) / 256, 256>>>();
    k_cvt_hist<<<(N_EDGES + 255) / 256, 256>>>(ei);
    k_scanA<<<SCAN_BLOCKS, 256>>>();
    k_scanB<<<1, 256>>>();
    k_scanC<<<SCAN_BLOCKS, 256>>>();
    k_scatter<<<(N_EDGES + 255) / 256, 256>>>();
    // log map
    k_logmap<<<(N_NODES * 32 + 255) / 256, 256>>>(x);
    // QKV projection (Q fp32, K/V fp16)
    {
        dim3 grid((N_NODES + 127) / 128, 3);
        k_gemmQKV<<<grid, 256>>>(xtan, Wq, Wk, Wv, q, kvh, N_NODES);
    }
    // attention aggregation
    k_agg<<<(N_NODES * 32 + 255) / 256, 256>>>();
    // output projection
    k_gemmO<<<(N_NODES + 127) / 128, 256>>>(agg, Wo, bo, otan, N_NODES);
    k_expmap<<<(N_NODES * 32 + 255) / 256, 256>>>(out);
}

// round 12
// speedup vs baseline: 2.9867x; 1.5428x over previous
#include <cuda_runtime.h>
#include <cuda_fp16.h>
#include <math.h>
#include <stdint.h>
#include <cstdint>

#define N_NODES 50000
#define N_EDGES 800000
#define D 128
#define HEADS 4
#define SCALEF 0.17677669529663687f   // 32^-0.5
#define EPSF 1e-7f
#define SCAN_BLOCKS ((N_NODES + 255) / 256)   // 196

// ---------------- static device scratch ----------------
__device__ __half g_xtanh[(size_t)N_NODES * D];      // x_tan fp16 (GEMM A)
__device__ __half g_wh[3 * D * D];                   // Wq|Wk|Wv fp16
__device__ float  g_q[(size_t)N_NODES * D];          // Q fp32
__device__ __half g_kvh[(size_t)N_NODES * 2 * D];    // per node: K(128)|V(128) fp16
__device__ float  g_agg[(size_t)N_NODES * D];        // attention out, pre-normalized
__device__ float  g_otan[(size_t)N_NODES * D];
__device__ int    g_rowbuf[N_EDGES];
__device__ int    g_colbuf[N_EDGES];
__device__ int    g_cnt[N_NODES];
__device__ int    g_off[N_NODES + 1];
__device__ int    g_cur[N_NODES];
__device__ int    g_esort[N_EDGES];
__device__ int    g_bsum[SCAN_BLOCKS];
__device__ int    g_boff[SCAN_BLOCKS];
__device__ int    g_is64;

// ---------------- edge dtype detect ----------------
__global__ void k_detect_edges(const unsigned int* __restrict__ w) {
    if (threadIdx.x == 0 && blockIdx.x == 0) {
        int all0 = 1;
        #pragma unroll
        for (int i = 0; i < 32; i++) all0 &= (w[2 * i + 1] == 0u);
        g_is64 = all0;
    }
}

__global__ void k_zero_cnt() {
    int i = blockIdx.x * blockDim.x + threadIdx.x;
    if (i < N_NODES) g_cnt[i] = 0;
}

__global__ void k_cvt_hist(const void* __restrict__ eiv) {
    int e = blockIdx.x * blockDim.x + threadIdx.x;
    if (e >= N_EDGES) return;
    int r, c;
    if (g_is64) {
        const long long* ei = (const long long*)eiv;
        r = (int)ei[e];
        c = (int)ei[N_EDGES + e];
    } else {
        const int* ei = (const int*)eiv;
        r = ei[e];
        c = ei[N_EDGES + e];
    }
    g_rowbuf[e] = r;
    g_colbuf[e] = c;
    atomicAdd(&g_cnt[c], 1);
}

// ---------------- parallel scan (3 phases) ----------------
__global__ __launch_bounds__(256)
void k_scanA() {
    int tid = threadIdx.x;
    int i = blockIdx.x * 256 + tid;
    int v = (i < N_NODES) ? g_cnt[i] : 0;
    int lane = tid & 31, wid = tid >> 5;
    int s = v;
    #pragma unroll
    for (int o = 1; o < 32; o <<= 1) {
        int t = __shfl_up_sync(0xFFFFFFFFu, s, o);
        if (lane >= o) s += t;
    }
    __shared__ int wsum[8];
    if (lane == 31) wsum[wid] = s;
    __syncthreads();
    if (wid == 0) {
        int ws = (lane < 8) ? wsum[lane] : 0;
        #pragma unroll
        for (int o = 1; o < 8; o <<= 1) {
            int t = __shfl_up_sync(0xFFFFFFFFu, ws, o);
            if (lane >= o) ws += t;
        }
        if (lane < 8) wsum[lane] = ws;
    }
    __syncthreads();
    int inc = s + ((wid > 0) ? wsum[wid - 1] : 0);
    if (i < N_NODES) g_off[i] = inc - v;
    if (tid == 255) g_bsum[blockIdx.x] = inc;
}

__global__ __launch_bounds__(256)
void k_scanB() {
    int tid = threadIdx.x;
    int v = (tid < SCAN_BLOCKS) ? g_bsum[tid] : 0;
    int lane = tid & 31, wid = tid >> 5;
    int s = v;
    #pragma unroll
    for (int o = 1; o < 32; o <<= 1) {
        int t = __shfl_up_sync(0xFFFFFFFFu, s, o);
        if (lane >= o) s += t;
    }
    __shared__ int wsum[8];
    if (lane == 31) wsum[wid] = s;
    __syncthreads();
    if (wid == 0) {
        int ws = (lane < 8) ? wsum[lane] : 0;
        #pragma unroll
        for (int o = 1; o < 8; o <<= 1) {
            int t = __shfl_up_sync(0xFFFFFFFFu, ws, o);
            if (lane >= o) ws += t;
        }
        if (lane < 8) wsum[lane] = ws;
    }
    __syncthreads();
    int inc = s + ((wid > 0) ? wsum[wid - 1] : 0);
    if (tid < SCAN_BLOCKS) g_boff[tid] = inc - v;
}

__global__ __launch_bounds__(256)
void k_scanC() {
    int i = blockIdx.x * 256 + threadIdx.x;
    if (i < N_NODES) {
        int o = g_off[i] + g_boff[blockIdx.x];
        g_off[i] = o;
        g_cur[i] = o;
    }
    if (i == 0) g_off[N_NODES] = N_EDGES;
}

__global__ void k_scatter() {
    int e = blockIdx.x * blockDim.x + threadIdx.x;
    if (e >= N_EDGES) return;
    int c = g_colbuf[e];
    int pos = atomicAdd(&g_cur[c], 1);
    g_esort[pos] = g_rowbuf[e];
}

// ---------------- convert W matrices to fp16 ----------------
__global__ void k_cvtW(const float* __restrict__ Wq, const float* __restrict__ Wk,
                       const float* __restrict__ Wv) {
    int i = blockIdx.x * blockDim.x + threadIdx.x;
    if (i >= 3 * D * D) return;
    int sel = i / (D * D);
    int off = i - sel * (D * D);
    float v = (sel == 0) ? Wq[off] : (sel == 1) ? Wk[off] : Wv[off];
    g_wh[i] = __float2half_rn(v);
}

// ---------------- Lorentz log map, warp per node, fp16 output ----------------
__global__ void k_logmap(const float* __restrict__ x) {
    int gw = (blockIdx.x * blockDim.x + threadIdx.x) >> 5;
    int lane = threadIdx.x & 31;
    if (gw >= N_NODES) return;
    const float* xr = x + (size_t)gw * 129;
    float a0 = xr[1 + 4 * lane + 0];
    float a1 = xr[1 + 4 * lane + 1];
    float a2 = xr[1 + 4 * lane + 2];
    float a3 = xr[1 + 4 * lane + 3];
    float ss = a0 * a0 + a1 * a1 + a2 * a2 + a3 * a3;
    #pragma unroll
    for (int o = 16; o >= 1; o >>= 1) ss += __shfl_xor_sync(0xFFFFFFFFu, ss, o);
    float norm = sqrtf(ss + EPSF);
    float fac = acoshf(fmaxf(xr[0], 1.0f + EPSF)) / norm;
    __half2 h0 = __float22half2_rn(make_float2(fac * a0, fac * a1));
    __half2 h1 = __float22half2_rn(make_float2(fac * a2, fac * a3));
    uint2 u;
    u.x = *reinterpret_cast<unsigned int*>(&h0);
    u.y = *reinterpret_cast<unsigned int*>(&h1);
    *(uint2*)(g_xtanh + (size_t)gw * D + 4 * lane) = u;
}

// ---------------- QKV GEMM via tensor cores (m16n8k16 fp16 -> fp32) ----------
// block: 128 rows x 128 cols, 8 warps each 32x64. K split in two 64-wide tiles.
__global__ __launch_bounds__(256, 2)
void k_gemmQKV_mma(const __half* __restrict__ A,
                   float* __restrict__ Q, __half* __restrict__ KV, int M) {
    __shared__ __half As[128][72];   // stride 72 halves = 9 x 16B (odd) -> conflict-free ldmatrix
    __shared__ __half Bs[128][72];
    int sel = blockIdx.y;
    const __half* W = g_wh + (size_t)sel * D * D;
    int t = threadIdx.x;
    int warp = t >> 5, lane = t & 31;
    int warp_m = warp & 3;
    int warp_n = warp >> 2;
    int rowBase = blockIdx.x * 128;

    float acc[2][8][4];
    #pragma unroll
    for (int i = 0; i < 2; i++)
        #pragma unroll
        for (int j = 0; j < 8; j++)
            #pragma unroll
            for (int k = 0; k < 4; k++) acc[i][j][k] = 0.f;

    for (int k0 = 0; k0 < 128; k0 += 64) {
        __syncthreads();
        // load A[128][64] and W[128][64] tiles (uint4 = 8 halves per chunk)
        #pragma unroll
        for (int c = t; c < 1024; c += 256) {
            int r = c >> 3, c8 = (c & 7) * 8;
            int gr = rowBase + r;
            uint4 va = make_uint4(0u, 0u, 0u, 0u);
            if (gr < M) va = *(const uint4*)&A[(size_t)gr * 128 + k0 + c8];
            *(uint4*)&As[r][c8] = va;
            uint4 vb = *(const uint4*)&W[(size_t)r * 128 + k0 + c8];
            *(uint4*)&Bs[r][c8] = vb;
        }
        __syncthreads();
        #pragma unroll
        for (int kk = 0; kk < 4; kk++) {
            uint32_t af[2][4];
            #pragma unroll
            for (int mt = 0; mt < 2; mt++) {
                int sub = lane >> 3;
                int row = warp_m * 32 + mt * 16 + ((sub & 1) * 8) + (lane & 7);
                int col = kk * 16 + ((sub >> 1) * 8);
                uint32_t addr = (uint32_t)__cvta_generic_to_shared(&As[row][col]);
                asm volatile("ldmatrix.sync.aligned.m8n8.x4.shared.b16 {%0,%1,%2,%3}, [%4];"
                    : "=r"(af[mt][0]), "=r"(af[mt][1]), "=r"(af[mt][2]), "=r"(af[mt][3])
                    : "r"(addr));
            }
            uint32_t bf[8][2];
            #pragma unroll
            for (int np = 0; np < 4; np++) {
                int sub = lane >> 3;
                int row = warp_n * 64 + np * 16 + ((sub >> 1) * 8) + (lane & 7);
                int col = kk * 16 + ((sub & 1) * 8);
                uint32_t r0, r1, r2, r3;
                uint32_t addr = (uint32_t)__cvta_generic_to_shared(&Bs[row][col]);
                asm volatile("ldmatrix.sync.aligned.m8n8.x4.shared.b16 {%0,%1,%2,%3}, [%4];"
                    : "=r"(r0), "=r"(r1), "=r"(r2), "=r"(r3) : "r"(addr));
                bf[np * 2][0] = r0; bf[np * 2][1] = r1;
                bf[np * 2 + 1][0] = r2; bf[np * 2 + 1][1] = r3;
            }
            #pragma unroll
            for (int mt = 0; mt < 2; mt++)
                #pragma unroll
                for (int nt = 0; nt < 8; nt++)
                    asm volatile("mma.sync.aligned.m16n8k16.row.col.f32.f16.f16.f32 "
                        "{%0,%1,%2,%3}, {%4,%5,%6,%7}, {%8,%9}, {%0,%1,%2,%3};"
                        : "+f"(acc[mt][nt][0]), "+f"(acc[mt][nt][1]),
                          "+f"(acc[mt][nt][2]), "+f"(acc[mt][nt][3])
                        : "r"(af[mt][0]), "r"(af[mt][1]), "r"(af[mt][2]), "r"(af[mt][3]),
                          "r"(bf[nt][0]), "r"(bf[nt][1]));
        }
    }
    // epilogue: c0,c1 -> row g, cols tg*2,+1 ; c2,c3 -> row g+8
    int g = lane >> 2, tg = lane & 3;
    #pragma unroll
    for (int mt = 0; mt < 2; mt++) {
        int r0 = rowBase + warp_m * 32 + mt * 16 + g;
        int r1 = r0 + 8;
        #pragma unroll
        for (int nt = 0; nt < 8; nt++) {
            int col = warp_n * 64 + nt * 8 + tg * 2;
            if (sel == 0) {
                if (r0 < M) *(float2*)&Q[(size_t)r0 * 128 + col] =
                    make_float2(acc[mt][nt][0], acc[mt][nt][1]);
                if (r1 < M) *(float2*)&Q[(size_t)r1 * 128 + col] =
                    make_float2(acc[mt][nt][2], acc[mt][nt][3]);
            } else {
                int off = (sel - 1) * 128;
                if (r0 < M) {
                    __half2 h = __float22half2_rn(make_float2(acc[mt][nt][0], acc[mt][nt][1]));
                    *(__half2*)&KV[(size_t)r0 * 256 + off + col] = h;
                }
                if (r1 < M) {
                    __half2 h = __float22half2_rn(make_float2(acc[mt][nt][2], acc[mt][nt][3]));
                    *(__half2*)&KV[(size_t)r1 * 256 + off + col] = h;
                }
            }
        }
    }
}

// ---------------- fp16 gather helper ----------------
__device__ __forceinline__ float4 ld4h(const __half* p) {
    uint2 u = *(const uint2*)p;
    __half2 h0 = *reinterpret_cast<__half2*>(&u.x);
    __half2 h1 = *reinterpret_cast<__half2*>(&u.y);
    float2 f0 = __half22float2(h0);
    float2 f1 = __half22float2(h1);
    return make_float4(f0.x, f0.y, f1.x, f1.y);
}

// ---------------- CSR aggregation: warp per dst, fp16 K/V, 2-way unroll ----
__global__ __launch_bounds__(256)
void k_agg() {
    int gw = (blockIdx.x * blockDim.x + threadIdx.x) >> 5;
    int lane = threadIdx.x & 31;
    if (gw >= N_NODES) return;
    int start = g_off[gw];
    int end   = g_off[gw + 1];
    float4 q = *(const float4*)(g_q + (size_t)gw * 128 + 4 * lane);
    float4 acc = make_float4(0.f, 0.f, 0.f, 0.f);
    float dsum = 0.f;
    int i = start;
    for (; i + 2 <= end; i += 2) {
        int s0 = g_esort[i];
        int s1 = g_esort[i + 1];
        const __half* b0 = g_kvh + (size_t)s0 * 256;
        const __half* b1 = g_kvh + (size_t)s1 * 256;
        float4 k0 = ld4h(b0 + 4 * lane);
        float4 k1 = ld4h(b1 + 4 * lane);
        float p0 = q.x * k0.x + q.y * k0.y + q.z * k0.z + q.w * k0.w;
        float p1 = q.x * k1.x + q.y * k1.y + q.z * k1.z + q.w * k1.w;
        p0 += __shfl_xor_sync(0xFFFFFFFFu, p0, 4);
        p1 += __shfl_xor_sync(0xFFFFFFFFu, p1, 4);
        p0 += __shfl_xor_sync(0xFFFFFFFFu, p0, 2);
        p1 += __shfl_xor_sync(0xFFFFFFFFu, p1, 2);
        p0 += __shfl_xor_sync(0xFFFFFFFFu, p0, 1);
        p1 += __shfl_xor_sync(0xFFFFFFFFu, p1, 1);
        float e0 = __expf(p0 * SCALEF);
        float e1 = __expf(p1 * SCALEF);
        float4 v0 = ld4h(b0 + 128 + 4 * lane);
        float4 v1 = ld4h(b1 + 128 + 4 * lane);
        dsum += e0 + e1;
        acc.x = fmaf(e0, v0.x, fmaf(e1, v1.x, acc.x));
        acc.y = fmaf(e0, v0.y, fmaf(e1, v1.y, acc.y));
        acc.z = fmaf(e0, v0.z, fmaf(e1, v1.z, acc.z));
        acc.w = fmaf(e0, v0.w, fmaf(e1, v1.w, acc.w));
    }
    if (i < end) {
        int s0 = g_esort[i];
        const __half* b0 = g_kvh + (size_t)s0 * 256;
        float4 k0 = ld4h(b0 + 4 * lane);
        float p0 = q.x * k0.x + q.y * k0.y + q.z * k0.z + q.w * k0.w;
        p0 += __shfl_xor_sync(0xFFFFFFFFu, p0, 4);
        p0 += __shfl_xor_sync(0xFFFFFFFFu, p0, 2);
        p0 += __shfl_xor_sync(0xFFFFFFFFu, p0, 1);
        float e0 = __expf(p0 * SCALEF);
        float4 v0 = ld4h(b0 + 128 + 4 * lane);
        dsum += e0;
        acc.x = fmaf(e0, v0.x, acc.x);
        acc.y = fmaf(e0, v0.y, acc.y);
        acc.z = fmaf(e0, v0.z, acc.z);
        acc.w = fmaf(e0, v0.w, acc.w);
    }
    float inv = (dsum > 0.f) ? (1.0f / dsum) : 0.f;
    float4 o = make_float4(acc.x * inv, acc.y * inv, acc.z * inv, acc.w * inv);
    *(float4*)(g_agg + (size_t)gw * 128 + 4 * lane) = o;
}

// ---------------- output GEMM 128x128x8 fp32 + bias ----------------
__global__ __launch_bounds__(256, 2)
void k_gemmO(const float* __restrict__ A, const float* __restrict__ B,
             const float* __restrict__ bias, float* __restrict__ C, int M) {
    __shared__ float As[8][132];
    __shared__ float Bs[8][132];
    int t = threadIdx.x;
    int rowBase = blockIdx.x * 128;
    int lr = t >> 1;
    int lk = (t & 1) * 4;
    int tx = t & 15, ty = t >> 4;
    float acc[8][8] = {};
    for (int kk = 0; kk < 128; kk += 8) {
        int r = rowBase + lr;
        float4 av = (r < M) ? *(const float4*)&A[(size_t)r * 128 + kk + lk]
                            : make_float4(0.f, 0.f, 0.f, 0.f);
        float4 bv = *(const float4*)&B[(size_t)lr * 128 + kk + lk];
        As[lk + 0][lr] = av.x; As[lk + 1][lr] = av.y;
        As[lk + 2][lr] = av.z; As[lk + 3][lr] = av.w;
        Bs[lk + 0][lr] = bv.x; Bs[lk + 1][lr] = bv.y;
        Bs[lk + 2][lr] = bv.z; Bs[lk + 3][lr] = bv.w;
        __syncthreads();
        #pragma unroll
        for (int k = 0; k < 8; k++) {
            float a[8], b[8];
            *(float4*)&a[0] = *(const float4*)&As[k][ty * 8];
            *(float4*)&a[4] = *(const float4*)&As[k][ty * 8 + 4];
            *(float4*)&b[0] = *(const float4*)&Bs[k][tx * 8];
            *(float4*)&b[4] = *(const float4*)&Bs[k][tx * 8 + 4];
            #pragma unroll
            for (int i = 0; i < 8; i++)
                #pragma unroll
                for (int j = 0; j < 8; j++)
                    acc[i][j] = fmaf(a[i], b[j], acc[i][j]);
        }
        __syncthreads();
    }
    #pragma unroll
    for (int i = 0; i < 8; i++) {
        int r = rowBase + ty * 8 + i;
        if (r >= M) continue;
        #pragma unroll
        for (int jj = 0; jj < 2; jj++) {
            int c = tx * 8 + jj * 4;
            float4 o = make_float4(acc[i][jj * 4 + 0] + bias[c + 0],
                                   acc[i][jj * 4 + 1] + bias[c + 1],
                                   acc[i][jj * 4 + 2] + bias[c + 2],
                                   acc[i][jj * 4 + 3] + bias[c + 3]);
            *(float4*)&C[(size_t)r * 128 + c] = o;
        }
    }
}

// ---------------- Lorentz exp map, warp per node ----------------
__global__ void k_expmap(float* __restrict__ out) {
    int gw = (blockIdx.x * blockDim.x + threadIdx.x) >> 5;
    int lane = threadIdx.x & 31;
    if (gw >= N_NODES) return;
    const float* vr = g_otan + (size_t)gw * D;
    float4 v = *(const float4*)(vr + 4 * lane);
    float ss = v.x * v.x + v.y * v.y + v.z * v.z + v.w * v.w;
    #pragma unroll
    for (int o = 16; o >= 1; o >>= 1) ss += __shfl_xor_sync(0xFFFFFFFFu, ss, o);
    float r = sqrtf(ss + EPSF);
    float x0 = coshf(r);
    float fac = sinhf(r) / r;
    float* orow = out + (size_t)gw * 129;
    if (lane == 0) orow[0] = x0;
    orow[1 + 4 * lane + 0] = fac * v.x;
    orow[1 + 4 * lane + 1] = fac * v.y;
    orow[1 + 4 * lane + 2] = fac * v.z;
    orow[1 + 4 * lane + 3] = fac * v.w;
}

// ---------------- launch ----------------
extern "C" void kernel_launch(void* const* d_in, const int* in_sizes, int n_in,
                              void* d_out, int out_size) {
    const float* x  = (const float*)d_in[0];
    const void*  ei = (const void*)d_in[1];
    const float* Wq = (const float*)d_in[2];
    const float* Wk = (const float*)d_in[3];
    const float* Wv = (const float*)d_in[4];
    const float* Wo = (const float*)d_in[5];
    const float* bo = (const float*)d_in[6];
    float* out      = (float*)d_out;
    (void)in_sizes; (void)n_in; (void)out_size;

    // real device addresses of __device__ globals (ATS pitfall!)
    float *q, *agg, *otan;
    __half *xtanh, *kvh;
    cudaGetSymbolAddress((void**)&xtanh, g_xtanh);
    cudaGetSymbolAddress((void**)&q,     g_q);
    cudaGetSymbolAddress((void**)&kvh,   g_kvh);
    cudaGetSymbolAddress((void**)&agg,   g_agg);
    cudaGetSymbolAddress((void**)&otan,  g_otan);

    // CSR build
    k_detect_edges<<<1, 32>>>((const unsigned int*)ei);
    k_zero_cnt<<<(N_NODES + 255) / 256, 256>>>();
    k_cvt_hist<<<(N_EDGES + 255) / 256, 256>>>(ei);
    k_scanA<<<SCAN_BLOCKS, 256>>>();
    k_scanB<<<1, 256>>>();
    k_scanC<<<SCAN_BLOCKS, 256>>>();
    k_scatter<<<(N_EDGES + 255) / 256, 256>>>();
    // weights -> fp16, log map -> fp16
    k_cvtW<<<(3 * D * D + 255) / 256, 256>>>(Wq, Wk, Wv);
    k_logmap<<<(N_NODES * 32 + 255) / 256, 256>>>(x);
    // QKV projection on tensor cores
    {
        dim3 grid((N_NODES + 127) / 128, 3);
        k_gemmQKV_mma<<<grid, 256>>>(xtanh, q, kvh, N_NODES);
    }
    // attention aggregation
    k_agg<<<(N_NODES * 32 + 255) / 256, 256>>>();
    // output projection (fp32)
    k_gemmO<<<(N_NODES + 127) / 128, 256>>>(agg, Wo, bo, otan, N_NODES);
    k_expmap<<<(N_NODES * 32 + 255) / 256, 256>>>(out);
}

// round 13
// speedup vs baseline: 3.5987x; 1.2049x over previous
#include <cuda_runtime.h>
#include <cuda_fp16.h>
#include <math.h>
#include <stdint.h>
#include <cstdint>

#define N_NODES 50000
#define N_EDGES 800000
#define D 128
#define HEADS 4
#define SCALEF 0.17677669529663687f   // 32^-0.5
#define EPSF 1e-7f
#define SCAN_BLOCKS ((N_NODES + 255) / 256)   // 196

// ---------------- static device scratch ----------------
__device__ __half g_xtanh[(size_t)N_NODES * D];      // x_tan fp16 (GEMM A)
__device__ __half g_wh[4 * D * D];                   // Wq|Wk|Wv|Wo fp16
__device__ float  g_q[(size_t)N_NODES * D];          // Q fp32
__device__ __half g_kvh[(size_t)N_NODES * 2 * D];    // per node: K(128)|V(128) fp16
__device__ __half g_aggh[(size_t)N_NODES * D];       // attention out fp16, pre-normalized
__device__ float  g_otan[(size_t)N_NODES * D];
__device__ int    g_rowbuf[N_EDGES];
__device__ int    g_colbuf[N_EDGES];
__device__ int    g_cnt[N_NODES];
__device__ int    g_off[N_NODES + 1];
__device__ int    g_cur[N_NODES];
__device__ int    g_esort[N_EDGES];
__device__ int    g_bsum[SCAN_BLOCKS];
__device__ int    g_boff[SCAN_BLOCKS];
__device__ int    g_is64;

// ---------------- edge dtype detect ----------------
__global__ void k_detect_edges(const unsigned int* __restrict__ w) {
    if (threadIdx.x == 0 && blockIdx.x == 0) {
        int all0 = 1;
        #pragma unroll
        for (int i = 0; i < 32; i++) all0 &= (w[2 * i + 1] == 0u);
        g_is64 = all0;
    }
}

__global__ void k_zero_cnt() {
    int i = blockIdx.x * blockDim.x + threadIdx.x;
    if (i < N_NODES) g_cnt[i] = 0;
}

__global__ void k_cvt_hist(const void* __restrict__ eiv) {
    int e = blockIdx.x * blockDim.x + threadIdx.x;
    if (e >= N_EDGES) return;
    int r, c;
    if (g_is64) {
        const long long* ei = (const long long*)eiv;
        r = (int)ei[e];
        c = (int)ei[N_EDGES + e];
    } else {
        const int* ei = (const int*)eiv;
        r = ei[e];
        c = ei[N_EDGES + e];
    }
    g_rowbuf[e] = r;
    g_colbuf[e] = c;
    atomicAdd(&g_cnt[c], 1);
}

// ---------------- parallel scan (3 phases) ----------------
__global__ __launch_bounds__(256)
void k_scanA() {
    int tid = threadIdx.x;
    int i = blockIdx.x * 256 + tid;
    int v = (i < N_NODES) ? g_cnt[i] : 0;
    int lane = tid & 31, wid = tid >> 5;
    int s = v;
    #pragma unroll
    for (int o = 1; o < 32; o <<= 1) {
        int t = __shfl_up_sync(0xFFFFFFFFu, s, o);
        if (lane >= o) s += t;
    }
    __shared__ int wsum[8];
    if (lane == 31) wsum[wid] = s;
    __syncthreads();
    if (wid == 0) {
        int ws = (lane < 8) ? wsum[lane] : 0;
        #pragma unroll
        for (int o = 1; o < 8; o <<= 1) {
            int t = __shfl_up_sync(0xFFFFFFFFu, ws, o);
            if (lane >= o) ws += t;
        }
        if (lane < 8) wsum[lane] = ws;
    }
    __syncthreads();
    int inc = s + ((wid > 0) ? wsum[wid - 1] : 0);
    if (i < N_NODES) g_off[i] = inc - v;
    if (tid == 255) g_bsum[blockIdx.x] = inc;
}

__global__ __launch_bounds__(256)
void k_scanB() {
    int tid = threadIdx.x;
    int v = (tid < SCAN_BLOCKS) ? g_bsum[tid] : 0;
    int lane = tid & 31, wid = tid >> 5;
    int s = v;
    #pragma unroll
    for (int o = 1; o < 32; o <<= 1) {
        int t = __shfl_up_sync(0xFFFFFFFFu, s, o);
        if (lane >= o) s += t;
    }
    __shared__ int wsum[8];
    if (lane == 31) wsum[wid] = s;
    __syncthreads();
    if (wid == 0) {
        int ws = (lane < 8) ? wsum[lane] : 0;
        #pragma unroll
        for (int o = 1; o < 8; o <<= 1) {
            int t = __shfl_up_sync(0xFFFFFFFFu, ws, o);
            if (lane >= o) ws += t;
        }
        if (lane < 8) wsum[lane] = ws;
    }
    __syncthreads();
    int inc = s + ((wid > 0) ? wsum[wid - 1] : 0);
    if (tid < SCAN_BLOCKS) g_boff[tid] = inc - v;
}

__global__ __launch_bounds__(256)
void k_scanC() {
    int i = blockIdx.x * 256 + threadIdx.x;
    if (i < N_NODES) {
        int o = g_off[i] + g_boff[blockIdx.x];
        g_off[i] = o;
        g_cur[i] = o;
    }
    if (i == 0) g_off[N_NODES] = N_EDGES;
}

__global__ void k_scatter() {
    int e = blockIdx.x * blockDim.x + threadIdx.x;
    if (e >= N_EDGES) return;
    int c = g_colbuf[e];
    int pos = atomicAdd(&g_cur[c], 1);
    g_esort[pos] = g_rowbuf[e];
}

// ---------------- convert W matrices to fp16 (Wq|Wk|Wv|Wo) ----------------
__global__ void k_cvtW(const float* __restrict__ Wq, const float* __restrict__ Wk,
                       const float* __restrict__ Wv, const float* __restrict__ Wo) {
    int i = blockIdx.x * blockDim.x + threadIdx.x;
    if (i >= 4 * D * D) return;
    int sel = i / (D * D);
    int off = i - sel * (D * D);
    float v = (sel == 0) ? Wq[off] : (sel == 1) ? Wk[off] : (sel == 2) ? Wv[off] : Wo[off];
    g_wh[i] = __float2half_rn(v);
}

// ---------------- Lorentz log map, warp per node, fp16 output ----------------
__global__ void k_logmap(const float* __restrict__ x) {
    int gw = (blockIdx.x * blockDim.x + threadIdx.x) >> 5;
    int lane = threadIdx.x & 31;
    if (gw >= N_NODES) return;
    const float* xr = x + (size_t)gw * 129;
    float a0 = xr[1 + 4 * lane + 0];
    float a1 = xr[1 + 4 * lane + 1];
    float a2 = xr[1 + 4 * lane + 2];
    float a3 = xr[1 + 4 * lane + 3];
    float ss = a0 * a0 + a1 * a1 + a2 * a2 + a3 * a3;
    #pragma unroll
    for (int o = 16; o >= 1; o >>= 1) ss += __shfl_xor_sync(0xFFFFFFFFu, ss, o);
    float norm = sqrtf(ss + EPSF);
    float fac = acoshf(fmaxf(xr[0], 1.0f + EPSF)) / norm;
    __half2 h0 = __float22half2_rn(make_float2(fac * a0, fac * a1));
    __half2 h1 = __float22half2_rn(make_float2(fac * a2, fac * a3));
    uint2 u;
    u.x = *reinterpret_cast<unsigned int*>(&h0);
    u.y = *reinterpret_cast<unsigned int*>(&h1);
    *(uint2*)(g_xtanh + (size_t)gw * D + 4 * lane) = u;
}

// ---------------- generic fp16 MMA GEMM (m16n8k16), 128x128 block ----------
// sel: 0=Q (fp32 out), 1=K (fp16 KV), 2=V (fp16 KV), 3=O (fp32 otan + bias)
__global__ __launch_bounds__(256, 2)
void k_gemm_mma(const __half* __restrict__ A,
                float* __restrict__ Fout, __half* __restrict__ KV,
                const float* __restrict__ bias, int selArg, int M) {
    __shared__ __half As[128][72];   // stride 72 halves (odd 16B units) -> conflict-free ldmatrix
    __shared__ __half Bs[128][72];
    int sel = (selArg >= 0) ? selArg : (int)blockIdx.y;
    const __half* W = g_wh + (size_t)sel * D * D;
    int t = threadIdx.x;
    int warp = t >> 5, lane = t & 31;
    int warp_m = warp & 3;
    int warp_n = warp >> 2;
    int rowBase = blockIdx.x * 128;

    float acc[2][8][4];
    #pragma unroll
    for (int i = 0; i < 2; i++)
        #pragma unroll
        for (int j = 0; j < 8; j++)
            #pragma unroll
            for (int k = 0; k < 4; k++) acc[i][j][k] = 0.f;

    for (int k0 = 0; k0 < 128; k0 += 64) {
        __syncthreads();
        #pragma unroll
        for (int c = t; c < 1024; c += 256) {
            int r = c >> 3, c8 = (c & 7) * 8;
            int gr = rowBase + r;
            uint4 va = make_uint4(0u, 0u, 0u, 0u);
            if (gr < M) va = *(const uint4*)&A[(size_t)gr * 128 + k0 + c8];
            *(uint4*)&As[r][c8] = va;
            uint4 vb = *(const uint4*)&W[(size_t)r * 128 + k0 + c8];
            *(uint4*)&Bs[r][c8] = vb;
        }
        __syncthreads();
        #pragma unroll
        for (int kk = 0; kk < 4; kk++) {
            uint32_t af[2][4];
            #pragma unroll
            for (int mt = 0; mt < 2; mt++) {
                int sub = lane >> 3;
                int row = warp_m * 32 + mt * 16 + ((sub & 1) * 8) + (lane & 7);
                int col = kk * 16 + ((sub >> 1) * 8);
                uint32_t addr = (uint32_t)__cvta_generic_to_shared(&As[row][col]);
                asm volatile("ldmatrix.sync.aligned.m8n8.x4.shared.b16 {%0,%1,%2,%3}, [%4];"
                    : "=r"(af[mt][0]), "=r"(af[mt][1]), "=r"(af[mt][2]), "=r"(af[mt][3])
                    : "r"(addr));
            }
            uint32_t bf[8][2];
            #pragma unroll
            for (int np = 0; np < 4; np++) {
                int sub = lane >> 3;
                int row = warp_n * 64 + np * 16 + ((sub >> 1) * 8) + (lane & 7);
                int col = kk * 16 + ((sub & 1) * 8);
                uint32_t r0, r1, r2, r3;
                uint32_t addr = (uint32_t)__cvta_generic_to_shared(&Bs[row][col]);
                asm volatile("ldmatrix.sync.aligned.m8n8.x4.shared.b16 {%0,%1,%2,%3}, [%4];"
                    : "=r"(r0), "=r"(r1), "=r"(r2), "=r"(r3) : "r"(addr));
                bf[np * 2][0] = r0; bf[np * 2][1] = r1;
                bf[np * 2 + 1][0] = r2; bf[np * 2 + 1][1] = r3;
            }
            #pragma unroll
            for (int mt = 0; mt < 2; mt++)
                #pragma unroll
                for (int nt = 0; nt < 8; nt++)
                    asm volatile("mma.sync.aligned.m16n8k16.row.col.f32.f16.f16.f32 "
                        "{%0,%1,%2,%3}, {%4,%5,%6,%7}, {%8,%9}, {%0,%1,%2,%3};"
                        : "+f"(acc[mt][nt][0]), "+f"(acc[mt][nt][1]),
                          "+f"(acc[mt][nt][2]), "+f"(acc[mt][nt][3])
                        : "r"(af[mt][0]), "r"(af[mt][1]), "r"(af[mt][2]), "r"(af[mt][3]),
                          "r"(bf[nt][0]), "r"(bf[nt][1]));
        }
    }
    int g = lane >> 2, tg = lane & 3;
    #pragma unroll
    for (int mt = 0; mt < 2; mt++) {
        int r0 = rowBase + warp_m * 32 + mt * 16 + g;
        int r1 = r0 + 8;
        #pragma unroll
        for (int nt = 0; nt < 8; nt++) {
            int col = warp_n * 64 + nt * 8 + tg * 2;
            if (sel == 0) {               // Q fp32
                if (r0 < M) *(float2*)&Fout[(size_t)r0 * 128 + col] =
                    make_float2(acc[mt][nt][0], acc[mt][nt][1]);
                if (r1 < M) *(float2*)&Fout[(size_t)r1 * 128 + col] =
                    make_float2(acc[mt][nt][2], acc[mt][nt][3]);
            } else if (sel == 3) {        // otan fp32 + bias
                float b0 = bias[col], b1 = bias[col + 1];
                if (r0 < M) *(float2*)&Fout[(size_t)r0 * 128 + col] =
                    make_float2(acc[mt][nt][0] + b0, acc[mt][nt][1] + b1);
                if (r1 < M) *(float2*)&Fout[(size_t)r1 * 128 + col] =
                    make_float2(acc[mt][nt][2] + b0, acc[mt][nt][3] + b1);
            } else {                      // K/V fp16
                int off = (sel - 1) * 128;
                if (r0 < M) {
                    __half2 h = __float22half2_rn(make_float2(acc[mt][nt][0], acc[mt][nt][1]));
                    *(__half2*)&KV[(size_t)r0 * 256 + off + col] = h;
                }
                if (r1 < M) {
                    __half2 h = __float22half2_rn(make_float2(acc[mt][nt][2], acc[mt][nt][3]));
                    *(__half2*)&KV[(size_t)r1 * 256 + off + col] = h;
                }
            }
        }
    }
}

// ---------------- fp16 gather helper ----------------
__device__ __forceinline__ float4 ld4h(const __half* p) {
    uint2 u = *(const uint2*)p;
    __half2 h0 = *reinterpret_cast<__half2*>(&u.x);
    __half2 h1 = *reinterpret_cast<__half2*>(&u.y);
    float2 f0 = __half22float2(h0);
    float2 f1 = __half22float2(h1);
    return make_float4(f0.x, f0.y, f1.x, f1.y);
}

// ---------------- CSR aggregation: warp per dst, 4-way unroll, fp16 out ----
__global__ __launch_bounds__(256)
void k_agg() {
    int gw = (blockIdx.x * blockDim.x + threadIdx.x) >> 5;
    int lane = threadIdx.x & 31;
    if (gw >= N_NODES) return;
    int start = g_off[gw];
    int end   = g_off[gw + 1];
    float4 q = *(const float4*)(g_q + (size_t)gw * 128 + 4 * lane);
    float4 acc = make_float4(0.f, 0.f, 0.f, 0.f);
    float dsum = 0.f;
    int i = start;
    for (; i + 4 <= end; i += 4) {
        int s0 = g_esort[i], s1 = g_esort[i + 1], s2 = g_esort[i + 2], s3 = g_esort[i + 3];
        const __half* b0 = g_kvh + (size_t)s0 * 256;
        const __half* b1 = g_kvh + (size_t)s1 * 256;
        const __half* b2 = g_kvh + (size_t)s2 * 256;
        const __half* b3 = g_kvh + (size_t)s3 * 256;
        float4 k0 = ld4h(b0 + 4 * lane);
        float4 k1 = ld4h(b1 + 4 * lane);
        float4 k2 = ld4h(b2 + 4 * lane);
        float4 k3 = ld4h(b3 + 4 * lane);
        float p0 = q.x * k0.x + q.y * k0.y + q.z * k0.z + q.w * k0.w;
        float p1 = q.x * k1.x + q.y * k1.y + q.z * k1.z + q.w * k1.w;
        float p2 = q.x * k2.x + q.y * k2.y + q.z * k2.z + q.w * k2.w;
        float p3 = q.x * k3.x + q.y * k3.y + q.z * k3.z + q.w * k3.w;
        #pragma unroll
        for (int o = 4; o >= 1; o >>= 1) {
            p0 += __shfl_xor_sync(0xFFFFFFFFu, p0, o);
            p1 += __shfl_xor_sync(0xFFFFFFFFu, p1, o);
            p2 += __shfl_xor_sync(0xFFFFFFFFu, p2, o);
            p3 += __shfl_xor_sync(0xFFFFFFFFu, p3, o);
        }
        float e0 = __expf(p0 * SCALEF);
        float e1 = __expf(p1 * SCALEF);
        float e2 = __expf(p2 * SCALEF);
        float e3 = __expf(p3 * SCALEF);
        float4 v0 = ld4h(b0 + 128 + 4 * lane);
        float4 v1 = ld4h(b1 + 128 + 4 * lane);
        float4 v2 = ld4h(b2 + 128 + 4 * lane);
        float4 v3 = ld4h(b3 + 128 + 4 * lane);
        dsum += (e0 + e1) + (e2 + e3);
        acc.x = fmaf(e0, v0.x, fmaf(e1, v1.x, fmaf(e2, v2.x, fmaf(e3, v3.x, acc.x))));
        acc.y = fmaf(e0, v0.y, fmaf(e1, v1.y, fmaf(e2, v2.y, fmaf(e3, v3.y, acc.y))));
        acc.z = fmaf(e0, v0.z, fmaf(e1, v1.z, fmaf(e2, v2.z, fmaf(e3, v3.z, acc.z))));
        acc.w = fmaf(e0, v0.w, fmaf(e1, v1.w, fmaf(e2, v2.w, fmaf(e3, v3.w, acc.w))));
    }
    for (; i < end; i++) {
        int s0 = g_esort[i];
        const __half* b0 = g_kvh + (size_t)s0 * 256;
        float4 k0 = ld4h(b0 + 4 * lane);
        float p0 = q.x * k0.x + q.y * k0.y + q.z * k0.z + q.w * k0.w;
        #pragma unroll
        for (int o = 4; o >= 1; o >>= 1) p0 += __shfl_xor_sync(0xFFFFFFFFu, p0, o);
        float e0 = __expf(p0 * SCALEF);
        float4 v0 = ld4h(b0 + 128 + 4 * lane);
        dsum += e0;
        acc.x = fmaf(e0, v0.x, acc.x);
        acc.y = fmaf(e0, v0.y, acc.y);
        acc.z = fmaf(e0, v0.z, acc.z);
        acc.w = fmaf(e0, v0.w, acc.w);
    }
    float inv = (dsum > 0.f) ? (1.0f / dsum) : 0.f;
    __half2 h0 = __float22half2_rn(make_float2(acc.x * inv, acc.y * inv));
    __half2 h1 = __float22half2_rn(make_float2(acc.z * inv, acc.w * inv));
    uint2 u;
    u.x = *reinterpret_cast<unsigned int*>(&h0);
    u.y = *reinterpret_cast<unsigned int*>(&h1);
    *(uint2*)(g_aggh + (size_t)gw * 128 + 4 * lane) = u;
}

// ---------------- Lorentz exp map, warp per node ----------------
__global__ void k_expmap(float* __restrict__ out) {
    int gw = (blockIdx.x * blockDim.x + threadIdx.x) >> 5;
    int lane = threadIdx.x & 31;
    if (gw >= N_NODES) return;
    const float* vr = g_otan + (size_t)gw * D;
    float4 v = *(const float4*)(vr + 4 * lane);
    float ss = v.x * v.x + v.y * v.y + v.z * v.z + v.w * v.w;
    #pragma unroll
    for (int o = 16; o >= 1; o >>= 1) ss += __shfl_xor_sync(0xFFFFFFFFu, ss, o);
    float r = sqrtf(ss + EPSF);
    float x0 = coshf(r);
    float fac = sinhf(r) / r;
    float* orow = out + (size_t)gw * 129;
    if (lane == 0) orow[0] = x0;
    orow[1 + 4 * lane + 0] = fac * v.x;
    orow[1 + 4 * lane + 1] = fac * v.y;
    orow[1 + 4 * lane + 2] = fac * v.z;
    orow[1 + 4 * lane + 3] = fac * v.w;
}

// ---------------- launch ----------------
extern "C" void kernel_launch(void* const* d_in, const int* in_sizes, int n_in,
                              void* d_out, int out_size) {
    const float* x  = (const float*)d_in[0];
    const void*  ei = (const void*)d_in[1];
    const float* Wq = (const float*)d_in[2];
    const float* Wk = (const float*)d_in[3];
    const float* Wv = (const float*)d_in[4];
    const float* Wo = (const float*)d_in[5];
    const float* bo = (const float*)d_in[6];
    float* out      = (float*)d_out;
    (void)in_sizes; (void)n_in; (void)out_size;

    // real device addresses of __device__ globals (ATS pitfall!)
    float *q, *otan;
    __half *xtanh, *kvh, *aggh;
    cudaGetSymbolAddress((void**)&xtanh, g_xtanh);
    cudaGetSymbolAddress((void**)&q,     g_q);
    cudaGetSymbolAddress((void**)&kvh,   g_kvh);
    cudaGetSymbolAddress((void**)&aggh,  g_aggh);
    cudaGetSymbolAddress((void**)&otan,  g_otan);

    // CSR build
    k_detect_edges<<<1, 32>>>((const unsigned int*)ei);
    k_zero_cnt<<<(N_NODES + 255) / 256, 256>>>();
    k_cvt_hist<<<(N_EDGES + 255) / 256, 256>>>(ei);
    k_scanA<<<SCAN_BLOCKS, 256>>>();
    k_scanB<<<1, 256>>>();
    k_scanC<<<SCAN_BLOCKS, 256>>>();
    k_scatter<<<(N_EDGES + 255) / 256, 256>>>();
    // weights -> fp16 (all 4), log map -> fp16
    k_cvtW<<<(4 * D * D + 255) / 256, 256>>>(Wq, Wk, Wv, Wo);
    k_logmap<<<(N_NODES * 32 + 255) / 256, 256>>>(x);
    // QKV projection on tensor cores (grid.y = sel 0..2)
    {
        dim3 grid((N_NODES + 127) / 128, 3);
        k_gemm_mma<<<grid, 256>>>(xtanh, q, kvh, nullptr, -1, N_NODES);
    }
    // attention aggregation (fp16 output)
    k_agg<<<(N_NODES * 32 + 255) / 256, 256>>>();
    // output projection on tensor cores (sel=3, bias)
    k_gemm_mma<<<(N_NODES + 127) / 128, 256>>>(aggh, otan, nullptr, bo, 3, N_NODES);
    k_expmap<<<(N_NODES * 32 + 255) / 256, 256>>>(out);
}